// round 11
// baseline (speedup 1.0000x reference)
#include <cuda_runtime.h>
#include <cuda_fp16.h>
#include <math.h>
#include <stdint.h>

#define PLANE 3145728            // 3072 * 1024
#define WELEMS 17825792          // 17 * 1024 * 1024

// ---------------- device scratch --------------------------------------------
__device__ float g_Y[PLANE];                 // pre-projection Y of current layer
__device__ float g_xt[17 * PLANE];           // xs[l] planes (fp32)
__device__ __half g_hX[2][PLANE];            // ping-pong fp16 X
__device__ __half g_hW[WELEMS];              // fp16 weights (W0 at 0, Ws at 1..16)

// ---------------- helpers -----------------------------------------------------
static __device__ __forceinline__ uint32_t smem_u32(const void* p) {
    return (uint32_t)__cvta_generic_to_shared(p);
}
static __device__ __forceinline__ void ldsm4(uint32_t* r, uint32_t addr) {
    asm volatile("ldmatrix.sync.aligned.m8n8.x4.shared.b16 {%0,%1,%2,%3}, [%4];"
        : "=r"(r[0]), "=r"(r[1]), "=r"(r[2]), "=r"(r[3]) : "r"(addr));
}
static __device__ __forceinline__ void mma16816(float* c, const uint32_t* a,
                                                uint32_t b0, uint32_t b1) {
    asm volatile("mma.sync.aligned.m16n8k16.row.col.f32.f16.f16.f32 "
        "{%0,%1,%2,%3}, {%4,%5,%6,%7}, {%8,%9}, {%0,%1,%2,%3};"
        : "+f"(c[0]), "+f"(c[1]), "+f"(c[2]), "+f"(c[3])
        : "r"(a[0]), "r"(a[1]), "r"(a[2]), "r"(a[3]), "r"(b0), "r"(b1));
}

// ---------------- weight conversion (fp16) -----------------------------------
__global__ void wconv_kernel(const float* __restrict__ W0, const float* __restrict__ Ws) {
    size_t i = (size_t)blockIdx.x * 256 + threadIdx.x;
    if (i >= (size_t)WELEMS) return;
    float v = (i < 1048576) ? W0[i] : Ws[i - 1048576];
    g_hW[i] = __float2half_rn(v);
}

// ---------------- prep: fp16 of input (ch2 transposed) -----------------------
__global__ void prep_kernel(const float* __restrict__ Xin) {
    int idx = blockIdx.x * 256 + threadIdx.x;
    if (idx >= PLANE) return;
    int d  = idx & 1023;
    int bc = idx >> 10;
    int c  = bc % 3;
    float v;
    if (c == 2) {
        int b = bc / 3;
        int dim = d >> 4, k = d & 15;
        v = Xin[((size_t)(b * 3 + 2)) * 1024 + k * 64 + dim];
    } else {
        v = Xin[idx];
    }
    g_hX[0][idx] = __float2half_rn(v);
}

// ---------------- fp16 mma.sync GEMM + fused epilogue ------------------------
// Tile 96x128 (256 CTAs), K-chunk 32, 3-stage cp.async, 8 warps (2M x 4N).
#define MAT_STRIDE_B 80                  // bytes per smem row (pad, conflict-free)
#define A_BYTES (96 * MAT_STRIDE_B)      // 7680
#define B_BYTES (128 * MAT_STRIDE_B)     // 10240
#define STAGE_BYTES (A_BYTES + B_BYTES)  // 17920
#define SMEM_TOTAL_G (3 * STAGE_BYTES)   // 53760

__global__ __launch_bounds__(256, 2) void tgemm_kernel(
    const float* __restrict__ bias, const float* __restrict__ hp, int layer)
{
    extern __shared__ __align__(16) char smem[];
    uint32_t sb = smem_u32(smem);

    int tid = threadIdx.x;
    int wid = tid >> 5, lane = tid & 31;
    int bx = blockIdx.x;
    int m0 = (bx >> 3) * 96;
    int n0 = (bx & 7) * 128;

    int par = layer & 1;
    const __half* srcA = g_hX[par] + (size_t)m0 * 1024;
    const __half* srcB = g_hW + (size_t)layer * 1048576 + (size_t)n0 * 1024;

    float acc[3][4][4];
#pragma unroll
    for (int i = 0; i < 3; i++)
#pragma unroll
        for (int j = 0; j < 4; j++)
#pragma unroll
            for (int k = 0; k < 4; k++) acc[i][j][k] = 0.f;

    auto issue = [&](int c, int st) {
#pragma unroll
        for (int u = 0; u < 4; u++) {
            int unit = tid + u * 256;        // 0..1023, use 0..895
            if (unit < 896) {
                uint32_t dst;
                const __half* gp;
                if (unit < 384) {            // A: 96 rows x 4 segs
                    int row = unit >> 2, seg = unit & 3;
                    dst = sb + st * STAGE_BYTES + row * MAT_STRIDE_B + seg * 16;
                    gp = srcA + (size_t)row * 1024 + c * 32 + seg * 8;
                } else {                     // B: 128 rows x 4 segs
                    int t = unit - 384;
                    int row = t >> 2, seg = t & 3;
                    dst = sb + st * STAGE_BYTES + A_BYTES + row * MAT_STRIDE_B + seg * 16;
                    gp = srcB + (size_t)row * 1024 + c * 32 + seg * 8;
                }
                asm volatile("cp.async.cg.shared.global [%0], [%1], 16;"
                    :: "r"(dst), "l"(gp));
            }
        }
        asm volatile("cp.async.commit_group;" ::: "memory");
    };

    issue(0, 0);
    issue(1, 1);

    int mw = (wid >> 2) * 48, nw = (wid & 3) * 32;
    int lrow = (lane & 7) + ((lane >> 3) & 1) * 8;
    int lcolB = ((lane >> 4) * 8) * 2;

    for (int c = 0; c < 32; c++) {
        int st = c % 3;
        if (c < 31) {
            asm volatile("cp.async.wait_group 1;" ::: "memory");
        } else {
            asm volatile("cp.async.wait_group 0;" ::: "memory");
        }
        __syncthreads();
        if (c + 2 < 32) issue(c + 2, (c + 2) % 3);

        uint32_t base = sb + st * STAGE_BYTES;
#pragma unroll
        for (int ks = 0; ks < 2; ks++) {
            int colb = ks * 32 + lcolB;
            uint32_t bh[2][4];
#pragma unroll
            for (int nb = 0; nb < 2; nb++)
                ldsm4(bh[nb], base + A_BYTES +
                              (nw + nb * 16 + lrow) * MAT_STRIDE_B + colb);
#pragma unroll
            for (int ma = 0; ma < 3; ma++) {
                uint32_t ah[4];
                ldsm4(ah, base + (mw + ma * 16 + lrow) * MAT_STRIDE_B + colb);
#pragma unroll
                for (int na = 0; na < 4; na++) {
                    int nb = na >> 1, hi = na & 1;
                    mma16816(acc[ma][na], ah, bh[nb][hi], bh[nb][2 + hi]);
                }
            }
        }
    }

    // ---- fused epilogue
    float hv = 0.f;
    const float* Xprev = nullptr;
    if (layer > 0) { hv = *hp; Xprev = g_xt + (size_t)(layer - 1) * PLANE; }
    float* PL = g_xt + (size_t)layer * PLANE;
    int opar = (layer + 1) & 1;
    int g = lane >> 2, t2 = (lane & 3) * 2;

#pragma unroll
    for (int ma = 0; ma < 3; ma++) {
#pragma unroll
        for (int na = 0; na < 4; na++) {
            int n = n0 + nw + na * 8 + t2;
            float2 b2 = make_float2(0.f, 0.f);
            if (layer > 0) b2 = *(const float2*)(bias + n);
#pragma unroll
            for (int hh = 0; hh < 2; hh++) {
                int m = m0 + mw + ma * 16 + g + hh * 8;
                float cx = acc[ma][na][hh * 2], cy = acc[ma][na][hh * 2 + 1];
                float2 y;
                if (layer > 0) {
                    float2 xo = *(const float2*)(Xprev + (size_t)m * 1024 + n);
                    y.x = xo.x + hv * fmaxf(cx + b2.x, 0.f);
                    y.y = xo.y + hv * fmaxf(cy + b2.y, 0.f);
                } else {
                    y.x = cx; y.y = cy;
                }
                if (m % 3 == 1) {          // S channel: no projection
                    *(float2*)(PL + (size_t)m * 1024 + n) = y;
                    __half2 h2;
                    h2.x = __float2half_rn(y.x);
                    h2.y = __float2half_rn(y.y);
                    *(__half2*)(&g_hX[opar][(size_t)m * 1024 + n]) = h2;
                } else {                   // U/V channels: polar input only
                    *(float2*)(g_Y + (size_t)m * 1024 + n) = y;
                }
            }
        }
    }
}

// ---------------- polar projection: 2 matrices per warp (ILP) ----------------
// Latency-bound chain -> interleave two independent matrices per warp.
// Phases: load | Gram | norm | iter0-collapsed | NS iters | U+store.
struct PM {
    float A[16][68];
    float Y[16][20];
    float Z[16][20];
    float T[16][20];
};   // 8192 bytes

__global__ __launch_bounds__(128) void polar_kernel(int plane, int nspecial,
                                                    int nclassic, float ca_s,
                                                    float cb_s, int opar) {
    extern __shared__ __align__(16) char psm[];
    PM* mats = (PM*)psm;
    int wwid = threadIdx.x >> 5, lane = threadIdx.x & 31;
    PM* MA = &mats[wwid * 2];
    PM* MB = MA + 1;

    int idxA = blockIdx.x * 8 + wwid * 2;
    int idxB = idxA + 1;
    int rowA = (idxA >> 1) * 3 + (idxA & 1) * 2;
    int rowB = (idxB >> 1) * 3 + (idxB & 1) * 2;
    const float* srcA = g_Y + (size_t)rowA * 1024;
    const float* srcB = g_Y + (size_t)rowB * 1024;
    size_t doffA = (size_t)rowA * 1024;
    size_t doffB = (size_t)rowB * 1024;

    int i0 = (lane >> 2) * 2, j0 = (lane & 3) * 4;
    int r0 = lane * 2;

    // ---- load both A matrices into col-major smem
#pragma unroll
    for (int q = 0; q < 4; q++) {
        float4 v0 = *(const float4*)(srcA + r0 * 16 + q * 4);
        float4 v1 = *(const float4*)(srcA + (r0 + 1) * 16 + q * 4);
        MA->A[q * 4 + 0][r0] = v0.x; MA->A[q * 4 + 1][r0] = v0.y;
        MA->A[q * 4 + 2][r0] = v0.z; MA->A[q * 4 + 3][r0] = v0.w;
        MA->A[q * 4 + 0][r0 + 1] = v1.x; MA->A[q * 4 + 1][r0 + 1] = v1.y;
        MA->A[q * 4 + 2][r0 + 1] = v1.z; MA->A[q * 4 + 3][r0 + 1] = v1.w;
    }
#pragma unroll
    for (int q = 0; q < 4; q++) {
        float4 v0 = *(const float4*)(srcB + r0 * 16 + q * 4);
        float4 v1 = *(const float4*)(srcB + (r0 + 1) * 16 + q * 4);
        MB->A[q * 4 + 0][r0] = v0.x; MB->A[q * 4 + 1][r0] = v0.y;
        MB->A[q * 4 + 2][r0] = v0.z; MB->A[q * 4 + 3][r0] = v0.w;
        MB->A[q * 4 + 0][r0 + 1] = v1.x; MB->A[q * 4 + 1][r0 + 1] = v1.y;
        MB->A[q * 4 + 2][r0 + 1] = v1.z; MB->A[q * 4 + 3][r0 + 1] = v1.w;
    }
    __syncwarp();

    // ---- Gram (both), write raw into Y
    float ga0[4] = {0, 0, 0, 0}, ga1[4] = {0, 0, 0, 0};
    float gb0[4] = {0, 0, 0, 0}, gb1[4] = {0, 0, 0, 0};
#pragma unroll
    for (int r = 0; r < 64; r += 4) {
        float4 a0 = *(const float4*)&MA->A[i0][r];
        float4 a1 = *(const float4*)&MA->A[i0 + 1][r];
#pragma unroll
        for (int t = 0; t < 4; t++) {
            float4 aj = *(const float4*)&MA->A[j0 + t][r];
            ga0[t] += a0.x * aj.x + a0.y * aj.y + a0.z * aj.z + a0.w * aj.w;
            ga1[t] += a1.x * aj.x + a1.y * aj.y + a1.z * aj.z + a1.w * aj.w;
        }
    }
#pragma unroll
    for (int r = 0; r < 64; r += 4) {
        float4 a0 = *(const float4*)&MB->A[i0][r];
        float4 a1 = *(const float4*)&MB->A[i0 + 1][r];
#pragma unroll
        for (int t = 0; t < 4; t++) {
            float4 aj = *(const float4*)&MB->A[j0 + t][r];
            gb0[t] += a0.x * aj.x + a0.y * aj.y + a0.z * aj.z + a0.w * aj.w;
            gb1[t] += a1.x * aj.x + a1.y * aj.y + a1.z * aj.z + a1.w * aj.w;
        }
    }
    *(float4*)&MA->Y[i0][j0]     = make_float4(ga0[0], ga0[1], ga0[2], ga0[3]);
    *(float4*)&MA->Y[i0 + 1][j0] = make_float4(ga1[0], ga1[1], ga1[2], ga1[3]);
    *(float4*)&MB->Y[i0][j0]     = make_float4(gb0[0], gb0[1], gb0[2], gb0[3]);
    *(float4*)&MB->Y[i0 + 1][j0] = make_float4(gb1[0], gb1[1], gb1[2], gb1[3]);
    __syncwarp();

    // ---- inf-norm (both)
    float rsA = 0.f, rsB = 0.f;
    if (lane < 16) {
#pragma unroll
        for (int j = 0; j < 16; j++) rsA += fabsf(MA->Y[lane][j]);
#pragma unroll
        for (int j = 0; j < 16; j++) rsB += fabsf(MB->Y[lane][j]);
    }
#pragma unroll
    for (int off = 16; off; off >>= 1) {
        rsA = fmaxf(rsA, __shfl_xor_sync(0xffffffffu, rsA, off));
        rsB = fmaxf(rsB, __shfl_xor_sync(0xffffffffu, rsB, off));
    }
    float invA = 1.0f / rsA, invB = 1.0f / rsB;

#pragma unroll
    for (int t = 0; t < 4; t++) {
        ga0[t] *= invA; ga1[t] *= invA;
        gb0[t] *= invB; gb1[t] *= invB;
    }
    *(float4*)&MA->Y[i0][j0]     = make_float4(ga0[0], ga0[1], ga0[2], ga0[3]);
    *(float4*)&MA->Y[i0 + 1][j0] = make_float4(ga1[0], ga1[1], ga1[2], ga1[3]);
    *(float4*)&MB->Y[i0][j0]     = make_float4(gb0[0], gb0[1], gb0[2], gb0[3]);
    *(float4*)&MB->Y[i0 + 1][j0] = make_float4(gb1[0], gb1[1], gb1[2], gb1[3]);
    __syncwarp();

    int ntot = nspecial + nclassic;

    // ---- iteration 0 (Z0 = I): S = Y*Y; Y1 = ca*Y + cb*S; Z1 = ca*I + cb*Y
    {
        float ca = (0 < nspecial) ? ca_s : 1.5f;
        float cb = (0 < nspecial) ? cb_s : -0.5f;
        float sa0[4] = {0, 0, 0, 0}, sa1[4] = {0, 0, 0, 0};
        float sb0[4] = {0, 0, 0, 0}, sb1[4] = {0, 0, 0, 0};
#pragma unroll
        for (int k = 0; k < 16; k++) {
            float ya = MA->Y[i0][k], yb = MA->Y[i0 + 1][k];
            float4 y4 = *(const float4*)&MA->Y[k][j0];
            sa0[0] += ya * y4.x; sa0[1] += ya * y4.y; sa0[2] += ya * y4.z; sa0[3] += ya * y4.w;
            sa1[0] += yb * y4.x; sa1[1] += yb * y4.y; sa1[2] += yb * y4.z; sa1[3] += yb * y4.w;
        }
#pragma unroll
        for (int k = 0; k < 16; k++) {
            float ya = MB->Y[i0][k], yb = MB->Y[i0 + 1][k];
            float4 y4 = *(const float4*)&MB->Y[k][j0];
            sb0[0] += ya * y4.x; sb0[1] += ya * y4.y; sb0[2] += ya * y4.z; sb0[3] += ya * y4.w;
            sb1[0] += yb * y4.x; sb1[1] += yb * y4.y; sb1[2] += yb * y4.z; sb1[3] += yb * y4.w;
        }
        __syncwarp();
        // Y1
        *(float4*)&MA->Y[i0][j0] = make_float4(ca * ga0[0] + cb * sa0[0], ca * ga0[1] + cb * sa0[1],
                                               ca * ga0[2] + cb * sa0[2], ca * ga0[3] + cb * sa0[3]);
        *(float4*)&MA->Y[i0 + 1][j0] = make_float4(ca * ga1[0] + cb * sa1[0], ca * ga1[1] + cb * sa1[1],
                                                   ca * ga1[2] + cb * sa1[2], ca * ga1[3] + cb * sa1[3]);
        *(float4*)&MB->Y[i0][j0] = make_float4(ca * gb0[0] + cb * sb0[0], ca * gb0[1] + cb * sb0[1],
                                               ca * gb0[2] + cb * sb0[2], ca * gb0[3] + cb * sb0[3]);
        *(float4*)&MB->Y[i0 + 1][j0] = make_float4(ca * gb1[0] + cb * sb1[0], ca * gb1[1] + cb * sb1[1],
                                                   ca * gb1[2] + cb * sb1[2], ca * gb1[3] + cb * sb1[3]);
        // Z1 = ca*I + cb*Y0 (from registers)
        *(float4*)&MA->Z[i0][j0] = make_float4(
            (i0 == j0 ? ca : 0.f) + cb * ga0[0], (i0 == j0 + 1 ? ca : 0.f) + cb * ga0[1],
            (i0 == j0 + 2 ? ca : 0.f) + cb * ga0[2], (i0 == j0 + 3 ? ca : 0.f) + cb * ga0[3]);
        *(float4*)&MA->Z[i0 + 1][j0] = make_float4(
            (i0 + 1 == j0 ? ca : 0.f) + cb * ga1[0], (i0 + 1 == j0 + 1 ? ca : 0.f) + cb * ga1[1],
            (i0 + 1 == j0 + 2 ? ca : 0.f) + cb * ga1[2], (i0 + 1 == j0 + 3 ? ca : 0.f) + cb * ga1[3]);
        *(float4*)&MB->Z[i0][j0] = make_float4(
            (i0 == j0 ? ca : 0.f) + cb * gb0[0], (i0 == j0 + 1 ? ca : 0.f) + cb * gb0[1],
            (i0 == j0 + 2 ? ca : 0.f) + cb * gb0[2], (i0 == j0 + 3 ? ca : 0.f) + cb * gb0[3]);
        *(float4*)&MB->Z[i0 + 1][j0] = make_float4(
            (i0 + 1 == j0 ? ca : 0.f) + cb * gb1[0], (i0 + 1 == j0 + 1 ? ca : 0.f) + cb * gb1[1],
            (i0 + 1 == j0 + 2 ? ca : 0.f) + cb * gb1[2], (i0 + 1 == j0 + 3 ? ca : 0.f) + cb * gb1[3]);
        __syncwarp();
    }

    for (int it = 1; it < ntot; it++) {
        float ca = (it < nspecial) ? ca_s : 1.5f;
        float cb = (it < nspecial) ? cb_s : -0.5f;
        bool lastit = (it == ntot - 1);

        // M = Z*Y -> T (raw), both mats
        {
            float t0[4] = {0, 0, 0, 0}, t1[4] = {0, 0, 0, 0};
            float s0[4] = {0, 0, 0, 0}, s1[4] = {0, 0, 0, 0};
#pragma unroll
            for (int k = 0; k < 16; k++) {
                float z0 = MA->Z[i0][k], z1 = MA->Z[i0 + 1][k];
                float4 y4 = *(const float4*)&MA->Y[k][j0];
                t0[0] += z0 * y4.x; t0[1] += z0 * y4.y; t0[2] += z0 * y4.z; t0[3] += z0 * y4.w;
                t1[0] += z1 * y4.x; t1[1] += z1 * y4.y; t1[2] += z1 * y4.z; t1[3] += z1 * y4.w;
            }
#pragma unroll
            for (int k = 0; k < 16; k++) {
                float z0 = MB->Z[i0][k], z1 = MB->Z[i0 + 1][k];
                float4 y4 = *(const float4*)&MB->Y[k][j0];
                s0[0] += z0 * y4.x; s0[1] += z0 * y4.y; s0[2] += z0 * y4.z; s0[3] += z0 * y4.w;
                s1[0] += z1 * y4.x; s1[1] += z1 * y4.y; s1[2] += z1 * y4.z; s1[3] += z1 * y4.w;
            }
            *(float4*)&MA->T[i0][j0]     = make_float4(t0[0], t0[1], t0[2], t0[3]);
            *(float4*)&MA->T[i0 + 1][j0] = make_float4(t1[0], t1[1], t1[2], t1[3]);
            *(float4*)&MB->T[i0][j0]     = make_float4(s0[0], s0[1], s0[2], s0[3]);
            *(float4*)&MB->T[i0 + 1][j0] = make_float4(s1[0], s1[1], s1[2], s1[3]);
        }
        __syncwarp();

        // Znew = ca*Z + cb*(Z*M); Ynew = ca*Y + cb*(Y*M) (skip Y on last)
        float zA0[4] = {0, 0, 0, 0}, zA1[4] = {0, 0, 0, 0};
        float yA0[4] = {0, 0, 0, 0}, yA1[4] = {0, 0, 0, 0};
        float zB0[4] = {0, 0, 0, 0}, zB1[4] = {0, 0, 0, 0};
        float yB0[4] = {0, 0, 0, 0}, yB1[4] = {0, 0, 0, 0};
#pragma unroll
        for (int k = 0; k < 16; k++) {
            float4 m4 = *(const float4*)&MA->T[k][j0];
            float za = MA->Z[i0][k], zb = MA->Z[i0 + 1][k];
            zA0[0] += za * m4.x; zA0[1] += za * m4.y; zA0[2] += za * m4.z; zA0[3] += za * m4.w;
            zA1[0] += zb * m4.x; zA1[1] += zb * m4.y; zA1[2] += zb * m4.z; zA1[3] += zb * m4.w;
            if (!lastit) {
                float ya = MA->Y[i0][k], yb = MA->Y[i0 + 1][k];
                yA0[0] += ya * m4.x; yA0[1] += ya * m4.y; yA0[2] += ya * m4.z; yA0[3] += ya * m4.w;
                yA1[0] += yb * m4.x; yA1[1] += yb * m4.y; yA1[2] += yb * m4.z; yA1[3] += yb * m4.w;
            }
        }
#pragma unroll
        for (int k = 0; k < 16; k++) {
            float4 m4 = *(const float4*)&MB->T[k][j0];
            float za = MB->Z[i0][k], zb = MB->Z[i0 + 1][k];
            zB0[0] += za * m4.x; zB0[1] += za * m4.y; zB0[2] += za * m4.z; zB0[3] += za * m4.w;
            zB1[0] += zb * m4.x; zB1[1] += zb * m4.y; zB1[2] += zb * m4.z; zB1[3] += zb * m4.w;
            if (!lastit) {
                float ya = MB->Y[i0][k], yb = MB->Y[i0 + 1][k];
                yB0[0] += ya * m4.x; yB0[1] += ya * m4.y; yB0[2] += ya * m4.z; yB0[3] += ya * m4.w;
                yB1[0] += yb * m4.x; yB1[1] += yb * m4.y; yB1[2] += yb * m4.z; yB1[3] += yb * m4.w;
            }
        }
        float4 zcA0 = *(const float4*)&MA->Z[i0][j0];
        float4 zcA1 = *(const float4*)&MA->Z[i0 + 1][j0];
        float4 zcB0 = *(const float4*)&MB->Z[i0][j0];
        float4 zcB1 = *(const float4*)&MB->Z[i0 + 1][j0];
        float4 ycA0, ycA1, ycB0, ycB1;
        if (!lastit) {
            ycA0 = *(const float4*)&MA->Y[i0][j0];
            ycA1 = *(const float4*)&MA->Y[i0 + 1][j0];
            ycB0 = *(const float4*)&MB->Y[i0][j0];
            ycB1 = *(const float4*)&MB->Y[i0 + 1][j0];
        }
        __syncwarp();
        *(float4*)&MA->Z[i0][j0] = make_float4(ca * zcA0.x + cb * zA0[0], ca * zcA0.y + cb * zA0[1],
                                               ca * zcA0.z + cb * zA0[2], ca * zcA0.w + cb * zA0[3]);
        *(float4*)&MA->Z[i0 + 1][j0] = make_float4(ca * zcA1.x + cb * zA1[0], ca * zcA1.y + cb * zA1[1],
                                                   ca * zcA1.z + cb * zA1[2], ca * zcA1.w + cb * zA1[3]);
        *(float4*)&MB->Z[i0][j0] = make_float4(ca * zcB0.x + cb * zB0[0], ca * zcB0.y + cb * zB0[1],
                                               ca * zcB0.z + cb * zB0[2], ca * zcB0.w + cb * zB0[3]);
        *(float4*)&MB->Z[i0 + 1][j0] = make_float4(ca * zcB1.x + cb * zB1[0], ca * zcB1.y + cb * zB1[1],
                                                   ca * zcB1.z + cb * zB1[2], ca * zcB1.w + cb * zB1[3]);
        if (!lastit) {
            *(float4*)&MA->Y[i0][j0] = make_float4(ca * ycA0.x + cb * yA0[0], ca * ycA0.y + cb * yA0[1],
                                                   ca * ycA0.z + cb * yA0[2], ca * ycA0.w + cb * yA0[3]);
            *(float4*)&MA->Y[i0 + 1][j0] = make_float4(ca * ycA1.x + cb * yA1[0], ca * ycA1.y + cb * yA1[1],
                                                       ca * ycA1.z + cb * yA1[2], ca * ycA1.w + cb * yA1[3]);
            *(float4*)&MB->Y[i0][j0] = make_float4(ca * ycB0.x + cb * yB0[0], ca * ycB0.y + cb * yB0[1],
                                                   ca * ycB0.z + cb * yB0[2], ca * ycB0.w + cb * yB0[3]);
            *(float4*)&MB->Y[i0 + 1][j0] = make_float4(ca * ycB1.x + cb * yB1[0], ca * ycB1.y + cb * yB1[1],
                                                       ca * ycB1.z + cb * yB1[2], ca * ycB1.w + cb * yB1[3]);
        }
        __syncwarp();
    }

    // ---- U = A * Z * s^(-1/2) and stores, per matrix
    float* plbase = g_xt + (size_t)plane * PLANE;
#pragma unroll
    for (int mm = 0; mm < 2; mm++) {
        PM* M = mm ? MB : MA;
        float isq = rsqrtf(mm ? rsB : rsA);
        size_t doff = mm ? doffB : doffA;
        float* dst = plbase + doff;

        float u0[16], u1[16];
#pragma unroll
        for (int c = 0; c < 16; c++) { u0[c] = 0.f; u1[c] = 0.f; }
#pragma unroll
        for (int k = 0; k < 16; k++) {
            float a0 = M->A[k][r0], a1 = M->A[k][r0 + 1];
#pragma unroll
            for (int cq = 0; cq < 4; cq++) {
                float4 z4 = *(const float4*)&M->Z[k][cq * 4];
                u0[cq * 4 + 0] += a0 * z4.x; u0[cq * 4 + 1] += a0 * z4.y;
                u0[cq * 4 + 2] += a0 * z4.z; u0[cq * 4 + 3] += a0 * z4.w;
                u1[cq * 4 + 0] += a1 * z4.x; u1[cq * 4 + 1] += a1 * z4.y;
                u1[cq * 4 + 2] += a1 * z4.z; u1[cq * 4 + 3] += a1 * z4.w;
            }
        }
#pragma unroll
        for (int c = 0; c < 16; c++) { u0[c] *= isq; u1[c] *= isq; }

        // fp32 out (lane's 128 contiguous bytes)
#pragma unroll
        for (int cq = 0; cq < 4; cq++) {
            *(float4*)(dst + r0 * 16 + cq * 4) =
                make_float4(u0[cq * 4], u0[cq * 4 + 1], u0[cq * 4 + 2], u0[cq * 4 + 3]);
            *(float4*)(dst + (r0 + 1) * 16 + cq * 4) =
                make_float4(u1[cq * 4], u1[cq * 4 + 1], u1[cq * 4 + 2], u1[cq * 4 + 3]);
        }

        // fp16 out direct (lane's 64 contiguous bytes)
        {
            __half* gh = g_hX[opar] + doff;
            uint32_t p[8];
#pragma unroll
            for (int cq = 0; cq < 8; cq++) {
                __half2 h2;
                h2.x = __float2half_rn(u0[2 * cq]);
                h2.y = __float2half_rn(u0[2 * cq + 1]);
                p[cq] = *(uint32_t*)&h2;
            }
            *(uint4*)(gh + r0 * 16)     = make_uint4(p[0], p[1], p[2], p[3]);
            *(uint4*)(gh + r0 * 16 + 8) = make_uint4(p[4], p[5], p[6], p[7]);
#pragma unroll
            for (int cq = 0; cq < 8; cq++) {
                __half2 h2;
                h2.x = __float2half_rn(u1[2 * cq]);
                h2.y = __float2half_rn(u1[2 * cq + 1]);
                p[cq] = *(uint32_t*)&h2;
            }
            *(uint4*)(gh + (r0 + 1) * 16)     = make_uint4(p[0], p[1], p[2], p[3]);
            *(uint4*)(gh + (r0 + 1) * 16 + 8) = make_uint4(p[4], p[5], p[6], p[7]);
        }
    }
}

// ---------------- X_transformed transpose ------------------------------------
__global__ void xt_kernel(float* __restrict__ out) {
    __shared__ float tile[256][18];
    int base = blockIdx.x * 256;
    int tid = threadIdx.x;
#pragma unroll
    for (int l = 0; l < 17; l++)
        tile[tid][l] = g_xt[(size_t)l * PLANE + base + tid];
    __syncthreads();
    float* o = out + (size_t)base * 17;
    for (int i = tid; i < 256 * 17; i += 256)
        o[i] = tile[i / 17][i % 17];
}

// ---------------- reconstruct + classify + softmax ----------------------------
__global__ __launch_bounds__(128) void classify_kernel(
    const float* __restrict__ Wc, const float* __restrict__ bc,
    float* __restrict__ out, int off_log)
{
    __shared__ float sU[1024], sS[256], sV[1024], sT[1024];
    __shared__ float sZ[4096];
    __shared__ float red[10 * 136];
    __shared__ float slog[10];

    int b = blockIdx.x, tid = threadIdx.x;
    const float* base = g_xt + (size_t)16 * PLANE + (size_t)b * 3 * 1024;

    for (int i = tid; i < 1024; i += 128) { sU[i] = base[i]; sV[i] = base[2048 + i]; }
    for (int i = tid; i < 256; i += 128) sS[i] = base[1024 + i];
    __syncthreads();

    for (int e = tid; e < 1024; e += 128) {
        int r = e >> 4, c = e & 15;
        float sum = 0.f;
#pragma unroll
        for (int k = 0; k < 16; k++) sum += sU[r * 16 + k] * sS[k * 16 + c];
        sT[e] = sum;
    }
    __syncthreads();

    for (int e = tid; e < 4096; e += 128) {
        int r = e >> 6, qn = e & 63;
        float sum = 0.f;
#pragma unroll
        for (int c = 0; c < 16; c++) sum += sT[r * 16 + c] * sV[qn * 16 + c];
        sZ[e] = sum;
    }
    __syncthreads();

    float acc[10];
#pragma unroll
    for (int n = 0; n < 10; n++) acc[n] = 0.f;
    for (int e = tid; e < 4096; e += 128) {
        float z = sZ[e];
#pragma unroll
        for (int n = 0; n < 10; n++) acc[n] += z * Wc[n * 4096 + e];
    }
#pragma unroll
    for (int n = 0; n < 10; n++) red[n * 136 + tid] = acc[n];
    __syncthreads();
    if (tid < 10) {
        float s = bc[tid];
        for (int j = 0; j < 128; j++) s += red[tid * 136 + j];
        slog[tid] = s;
    }
    __syncthreads();
    if (tid == 0) {
        float mx = slog[0];
        for (int n = 1; n < 10; n++) mx = fmaxf(mx, slog[n]);
        float ex[10]; float se = 0.f;
        for (int n = 0; n < 10; n++) { ex[n] = expf(slog[n] - mx); se += ex[n]; }
        float inv = 1.f / se;
        for (int n = 0; n < 10; n++) {
            out[b * 10 + n] = ex[n] * inv;
            if (off_log >= 0) out[off_log + b * 10 + n] = slog[n];
        }
    }
}

// ---------------- launch ------------------------------------------------------
extern "C" void kernel_launch(void* const* d_in, const int* in_sizes, int n_in,
                              void* d_out, int out_size) {
    const float* X  = (const float*)d_in[0];
    const float* h  = (const float*)d_in[1];
    const float* W0 = (const float*)d_in[2];
    const float* Ws = (const float*)d_in[3];
    const float* bs = (const float*)d_in[4];
    const float* Wc = (const float*)d_in[5];
    const float* bc = (const float*)d_in[6];
    float* out = (float*)d_out;

    int off_log = -1, off_xt = -1;
    if (out_size >= 10240 + 10240 + 53477376) { off_log = 10240; off_xt = 20480; }
    else if (out_size == 10240 + 53477376)    { off_xt = 10240; }
    else if (out_size >= 20480)               { off_log = 10240; }

    cudaFuncSetAttribute(tgemm_kernel, cudaFuncAttributeMaxDynamicSharedMemorySize,
                         SMEM_TOTAL_G);
    cudaFuncSetAttribute(polar_kernel, cudaFuncAttributeMaxDynamicSharedMemorySize,
                         65536);

    wconv_kernel<<<WELEMS / 256, 256>>>(W0, Ws);
    prep_kernel<<<PLANE / 256, 256>>>(X);

    tgemm_kernel<<<256, 256, SMEM_TOTAL_G>>>(nullptr, h, 0);
    polar_kernel<<<256, 128, 65536>>>(0, 4, 5, 2.4f, -1.4f, 1);   // layer 0
    for (int l = 1; l <= 16; l++) {
        tgemm_kernel<<<256, 256, SMEM_TOTAL_G>>>(bs + (size_t)(l - 1) * 1024, h, l);
        polar_kernel<<<256, 128, 65536>>>(l, 1, 2, 1.9f, -0.9f, (l + 1) & 1);
    }

    if (off_xt >= 0)
        xt_kernel<<<PLANE / 256, 256>>>(out + off_xt);
    classify_kernel<<<1024, 128>>>(Wc, bc, out, off_log);
}

// round 12
// speedup vs baseline: 1.5253x; 1.5253x over previous
#include <cuda_runtime.h>
#include <cuda_fp16.h>
#include <math.h>
#include <stdint.h>

#define PLANE 3145728            // 3072 * 1024
#define WELEMS 17825792          // 17 * 1024 * 1024

// ---------------- device scratch --------------------------------------------
__device__ float g_Y[PLANE];                 // pre-projection Y of current layer
__device__ float g_xt[17 * PLANE];           // xs[l] planes (fp32)
__device__ __half g_hX[2][PLANE];            // ping-pong fp16 X
__device__ __half g_hW[WELEMS];              // fp16 weights (W0 at 0, Ws at 1..16)

// ---------------- helpers -----------------------------------------------------
static __device__ __forceinline__ uint32_t smem_u32(const void* p) {
    return (uint32_t)__cvta_generic_to_shared(p);
}
static __device__ __forceinline__ void ldsm4(uint32_t* r, uint32_t addr) {
    asm volatile("ldmatrix.sync.aligned.m8n8.x4.shared.b16 {%0,%1,%2,%3}, [%4];"
        : "=r"(r[0]), "=r"(r[1]), "=r"(r[2]), "=r"(r[3]) : "r"(addr));
}
static __device__ __forceinline__ void mma16816(float* c, const uint32_t* a,
                                                uint32_t b0, uint32_t b1) {
    asm volatile("mma.sync.aligned.m16n8k16.row.col.f32.f16.f16.f32 "
        "{%0,%1,%2,%3}, {%4,%5,%6,%7}, {%8,%9}, {%0,%1,%2,%3};"
        : "+f"(c[0]), "+f"(c[1]), "+f"(c[2]), "+f"(c[3])
        : "r"(a[0]), "r"(a[1]), "r"(a[2]), "r"(a[3]), "r"(b0), "r"(b1));
}

// ---------------- weight conversion (fp16) -----------------------------------
__global__ void wconv_kernel(const float* __restrict__ W0, const float* __restrict__ Ws) {
    size_t i = (size_t)blockIdx.x * 256 + threadIdx.x;
    if (i >= (size_t)WELEMS) return;
    float v = (i < 1048576) ? W0[i] : Ws[i - 1048576];
    g_hW[i] = __float2half_rn(v);
}

// ---------------- prep: fp16 of input (ch2 transposed) -----------------------
__global__ void prep_kernel(const float* __restrict__ Xin) {
    int idx = blockIdx.x * 256 + threadIdx.x;
    if (idx >= PLANE) return;
    int d  = idx & 1023;
    int bc = idx >> 10;
    int c  = bc % 3;
    float v;
    if (c == 2) {
        int b = bc / 3;
        int dim = d >> 4, k = d & 15;
        v = Xin[((size_t)(b * 3 + 2)) * 1024 + k * 64 + dim];
    } else {
        v = Xin[idx];
    }
    g_hX[0][idx] = __float2half_rn(v);
}

// ---------------- fp16 mma.sync GEMM + fused epilogue ------------------------
// Tile 96x128 (256 CTAs), K-chunk 32, 3-stage cp.async, 8 warps (2M x 4N).
#define MAT_STRIDE_B 80                  // bytes per smem row (pad, conflict-free)
#define A_BYTES (96 * MAT_STRIDE_B)      // 7680
#define B_BYTES (128 * MAT_STRIDE_B)     // 10240
#define STAGE_BYTES (A_BYTES + B_BYTES)  // 17920
#define SMEM_TOTAL_G (3 * STAGE_BYTES)   // 53760

__global__ __launch_bounds__(256, 2) void tgemm_kernel(
    const float* __restrict__ bias, const float* __restrict__ hp, int layer)
{
    extern __shared__ __align__(16) char smem[];
    uint32_t sb = smem_u32(smem);

    int tid = threadIdx.x;
    int wid = tid >> 5, lane = tid & 31;
    int bx = blockIdx.x;
    int m0 = (bx >> 3) * 96;
    int n0 = (bx & 7) * 128;

    int par = layer & 1;
    const __half* srcA = g_hX[par] + (size_t)m0 * 1024;
    const __half* srcB = g_hW + (size_t)layer * 1048576 + (size_t)n0 * 1024;

    float acc[3][4][4];
#pragma unroll
    for (int i = 0; i < 3; i++)
#pragma unroll
        for (int j = 0; j < 4; j++)
#pragma unroll
            for (int k = 0; k < 4; k++) acc[i][j][k] = 0.f;

    auto issue = [&](int c, int st) {
#pragma unroll
        for (int u = 0; u < 4; u++) {
            int unit = tid + u * 256;        // 0..1023, use 0..895
            if (unit < 896) {
                uint32_t dst;
                const __half* gp;
                if (unit < 384) {            // A: 96 rows x 4 segs
                    int row = unit >> 2, seg = unit & 3;
                    dst = sb + st * STAGE_BYTES + row * MAT_STRIDE_B + seg * 16;
                    gp = srcA + (size_t)row * 1024 + c * 32 + seg * 8;
                } else {                     // B: 128 rows x 4 segs
                    int t = unit - 384;
                    int row = t >> 2, seg = t & 3;
                    dst = sb + st * STAGE_BYTES + A_BYTES + row * MAT_STRIDE_B + seg * 16;
                    gp = srcB + (size_t)row * 1024 + c * 32 + seg * 8;
                }
                asm volatile("cp.async.cg.shared.global [%0], [%1], 16;"
                    :: "r"(dst), "l"(gp));
            }
        }
        asm volatile("cp.async.commit_group;" ::: "memory");
    };

    issue(0, 0);
    issue(1, 1);

    int mw = (wid >> 2) * 48, nw = (wid & 3) * 32;
    int lrow = (lane & 7) + ((lane >> 3) & 1) * 8;
    int lcolB = ((lane >> 4) * 8) * 2;

    for (int c = 0; c < 32; c++) {
        int st = c % 3;
        if (c < 31) {
            asm volatile("cp.async.wait_group 1;" ::: "memory");
        } else {
            asm volatile("cp.async.wait_group 0;" ::: "memory");
        }
        __syncthreads();
        if (c + 2 < 32) issue(c + 2, (c + 2) % 3);

        uint32_t base = sb + st * STAGE_BYTES;
#pragma unroll
        for (int ks = 0; ks < 2; ks++) {
            int colb = ks * 32 + lcolB;
            uint32_t bh[2][4];
#pragma unroll
            for (int nb = 0; nb < 2; nb++)
                ldsm4(bh[nb], base + A_BYTES +
                              (nw + nb * 16 + lrow) * MAT_STRIDE_B + colb);
#pragma unroll
            for (int ma = 0; ma < 3; ma++) {
                uint32_t ah[4];
                ldsm4(ah, base + (mw + ma * 16 + lrow) * MAT_STRIDE_B + colb);
#pragma unroll
                for (int na = 0; na < 4; na++) {
                    int nb = na >> 1, hi = na & 1;
                    mma16816(acc[ma][na], ah, bh[nb][hi], bh[nb][2 + hi]);
                }
            }
        }
    }

    // ---- fused epilogue
    float hv = 0.f;
    const float* Xprev = nullptr;
    if (layer > 0) { hv = *hp; Xprev = g_xt + (size_t)(layer - 1) * PLANE; }
    float* PL = g_xt + (size_t)layer * PLANE;
    int opar = (layer + 1) & 1;
    int g = lane >> 2, t2 = (lane & 3) * 2;

#pragma unroll
    for (int ma = 0; ma < 3; ma++) {
#pragma unroll
        for (int na = 0; na < 4; na++) {
            int n = n0 + nw + na * 8 + t2;
            float2 b2 = make_float2(0.f, 0.f);
            if (layer > 0) b2 = *(const float2*)(bias + n);
#pragma unroll
            for (int hh = 0; hh < 2; hh++) {
                int m = m0 + mw + ma * 16 + g + hh * 8;
                float cx = acc[ma][na][hh * 2], cy = acc[ma][na][hh * 2 + 1];
                float2 y;
                if (layer > 0) {
                    float2 xo = *(const float2*)(Xprev + (size_t)m * 1024 + n);
                    y.x = xo.x + hv * fmaxf(cx + b2.x, 0.f);
                    y.y = xo.y + hv * fmaxf(cy + b2.y, 0.f);
                } else {
                    y.x = cx; y.y = cy;
                }
                if (m % 3 == 1) {          // S channel: no projection
                    *(float2*)(PL + (size_t)m * 1024 + n) = y;
                    __half2 h2;
                    h2.x = __float2half_rn(y.x);
                    h2.y = __float2half_rn(y.y);
                    *(__half2*)(&g_hX[opar][(size_t)m * 1024 + n]) = h2;
                } else {                   // U/V channels: polar input only
                    *(float2*)(g_Y + (size_t)m * 1024 + n) = y;
                }
            }
        }
    }
}

// ---------------- polar projection (restructured Newton-Schulz) --------------
// R10 structure (best known). Iter 0 collapsed; shared-M updates; last-iter
// Y-update skipped; fp16 output stored directly (no smem pack round-trip).
#define PNW 4
__global__ __launch_bounds__(128) void polar_kernel(int plane, int nspecial,
                                                    int nclassic, float ca_s,
                                                    float cb_s, int opar) {
    __shared__ float AsP[PNW][16][68];
    __shared__ float MsP[PNW][3][16][20];

    int w = threadIdx.x >> 5, lane = threadIdx.x & 31;
    int idx = blockIdx.x * PNW + w;
    int b = idx >> 1, ch = (idx & 1) * 2;

    const float* src = g_Y + (size_t)(b * 3 + ch) * 1024;
    size_t doff = (size_t)(b * 3 + ch) * 1024;
    float* dst = g_xt + (size_t)plane * PLANE + doff;

    float (*A)[68]  = AsP[w];
    float (*Ym)[20] = MsP[w][0];
    float (*Zm)[20] = MsP[w][1];
    float (*Tm)[20] = MsP[w][2];

    int r0 = lane * 2;
    float a0r[16], a1r[16];            // own two A rows kept in registers
#pragma unroll
    for (int qq = 0; qq < 4; qq++) {
        float4 v0 = *(const float4*)(src + r0 * 16 + qq * 4);
        float4 v1 = *(const float4*)(src + (r0 + 1) * 16 + qq * 4);
        a0r[qq * 4 + 0] = v0.x; a0r[qq * 4 + 1] = v0.y;
        a0r[qq * 4 + 2] = v0.z; a0r[qq * 4 + 3] = v0.w;
        a1r[qq * 4 + 0] = v1.x; a1r[qq * 4 + 1] = v1.y;
        a1r[qq * 4 + 2] = v1.z; a1r[qq * 4 + 3] = v1.w;
        A[qq * 4 + 0][r0] = v0.x; A[qq * 4 + 1][r0] = v0.y;
        A[qq * 4 + 2][r0] = v0.z; A[qq * 4 + 3][r0] = v0.w;
        A[qq * 4 + 0][r0 + 1] = v1.x; A[qq * 4 + 1][r0 + 1] = v1.y;
        A[qq * 4 + 2][r0 + 1] = v1.z; A[qq * 4 + 3][r0 + 1] = v1.w;
    }
    __syncwarp();

    int i0 = (lane >> 2) * 2, j0 = (lane & 3) * 4;
    float g0[4] = {0, 0, 0, 0}, g1[4] = {0, 0, 0, 0};
#pragma unroll
    for (int r = 0; r < 64; r += 4) {
        float4 a0 = *(const float4*)&A[i0][r];
        float4 a1 = *(const float4*)&A[i0 + 1][r];
#pragma unroll
        for (int t = 0; t < 4; t++) {
            float4 aj = *(const float4*)&A[j0 + t][r];
            g0[t] += a0.x * aj.x + a0.y * aj.y + a0.z * aj.z + a0.w * aj.w;
            g1[t] += a1.x * aj.x + a1.y * aj.y + a1.z * aj.z + a1.w * aj.w;
        }
    }
    *(float4*)&Ym[i0][j0]     = make_float4(g0[0], g0[1], g0[2], g0[3]);
    *(float4*)&Ym[i0 + 1][j0] = make_float4(g1[0], g1[1], g1[2], g1[3]);
    __syncwarp();

    float rs = 0.f;
    if (lane < 16) {
#pragma unroll
        for (int j = 0; j < 16; j++) rs += fabsf(Ym[lane][j]);
    }
#pragma unroll
    for (int off = 16; off; off >>= 1)
        rs = fmaxf(rs, __shfl_xor_sync(0xffffffffu, rs, off));
    float invs = 1.0f / rs;

#pragma unroll
    for (int t = 0; t < 4; t++) { g0[t] *= invs; g1[t] *= invs; }
    *(float4*)&Ym[i0][j0]     = make_float4(g0[0], g0[1], g0[2], g0[3]);
    *(float4*)&Ym[i0 + 1][j0] = make_float4(g1[0], g1[1], g1[2], g1[3]);
    __syncwarp();

    int ntot = nspecial + nclassic;

    // ---- iteration 0 (Z0 = I): S = Y*Y; Y1 = ca*Y + cb*S; Z1 = ca*I + cb*Y
    {
        float ca = (0 < nspecial) ? ca_s : 1.5f;
        float cb = (0 < nspecial) ? cb_s : -0.5f;
        float s0[4] = {0, 0, 0, 0}, s1[4] = {0, 0, 0, 0};
#pragma unroll
        for (int k = 0; k < 16; k++) {
            float ya = Ym[i0][k], yb = Ym[i0 + 1][k];
            float4 y4 = *(const float4*)&Ym[k][j0];
            s0[0] += ya * y4.x; s0[1] += ya * y4.y; s0[2] += ya * y4.z; s0[3] += ya * y4.w;
            s1[0] += yb * y4.x; s1[1] += yb * y4.y; s1[2] += yb * y4.z; s1[3] += yb * y4.w;
        }
        float4 yc0 = *(const float4*)&Ym[i0][j0];
        float4 yc1 = *(const float4*)&Ym[i0 + 1][j0];
        __syncwarp();
        *(float4*)&Ym[i0][j0] = make_float4(ca * yc0.x + cb * s0[0], ca * yc0.y + cb * s0[1],
                                            ca * yc0.z + cb * s0[2], ca * yc0.w + cb * s0[3]);
        *(float4*)&Ym[i0 + 1][j0] = make_float4(ca * yc1.x + cb * s1[0], ca * yc1.y + cb * s1[1],
                                                ca * yc1.z + cb * s1[2], ca * yc1.w + cb * s1[3]);
        *(float4*)&Zm[i0][j0] = make_float4(
            (i0 == j0 ? ca : 0.f) + cb * yc0.x, (i0 == j0 + 1 ? ca : 0.f) + cb * yc0.y,
            (i0 == j0 + 2 ? ca : 0.f) + cb * yc0.z, (i0 == j0 + 3 ? ca : 0.f) + cb * yc0.w);
        *(float4*)&Zm[i0 + 1][j0] = make_float4(
            (i0 + 1 == j0 ? ca : 0.f) + cb * yc1.x, (i0 + 1 == j0 + 1 ? ca : 0.f) + cb * yc1.y,
            (i0 + 1 == j0 + 2 ? ca : 0.f) + cb * yc1.z, (i0 + 1 == j0 + 3 ? ca : 0.f) + cb * yc1.w);
        __syncwarp();
    }

    for (int it = 1; it < ntot; it++) {
        float ca = (it < nspecial) ? ca_s : 1.5f;
        float cb = (it < nspecial) ? cb_s : -0.5f;
        bool lastit = (it == ntot - 1);

        // M = Z*Y -> Tm (raw)
        float t0[4] = {0, 0, 0, 0}, t1[4] = {0, 0, 0, 0};
#pragma unroll
        for (int k = 0; k < 16; k++) {
            float z0 = Zm[i0][k], z1 = Zm[i0 + 1][k];
            float4 y4 = *(const float4*)&Ym[k][j0];
            t0[0] += z0 * y4.x; t0[1] += z0 * y4.y; t0[2] += z0 * y4.z; t0[3] += z0 * y4.w;
            t1[0] += z1 * y4.x; t1[1] += z1 * y4.y; t1[2] += z1 * y4.z; t1[3] += z1 * y4.w;
        }
        *(float4*)&Tm[i0][j0]     = make_float4(t0[0], t0[1], t0[2], t0[3]);
        *(float4*)&Tm[i0 + 1][j0] = make_float4(t1[0], t1[1], t1[2], t1[3]);
        __syncwarp();

        // Ynew = ca*Y + cb*(Y*M); Znew = ca*Z + cb*(Z*M)  (shared M float4 reads)
        float yn0[4] = {0, 0, 0, 0}, yn1[4] = {0, 0, 0, 0};
        float zn0[4] = {0, 0, 0, 0}, zn1[4] = {0, 0, 0, 0};
#pragma unroll
        for (int k = 0; k < 16; k++) {
            float4 m4 = *(const float4*)&Tm[k][j0];
            float za = Zm[i0][k], zb = Zm[i0 + 1][k];
            zn0[0] += za * m4.x; zn0[1] += za * m4.y; zn0[2] += za * m4.z; zn0[3] += za * m4.w;
            zn1[0] += zb * m4.x; zn1[1] += zb * m4.y; zn1[2] += zb * m4.z; zn1[3] += zb * m4.w;
            if (!lastit) {
                float ya = Ym[i0][k], yb = Ym[i0 + 1][k];
                yn0[0] += ya * m4.x; yn0[1] += ya * m4.y; yn0[2] += ya * m4.z; yn0[3] += ya * m4.w;
                yn1[0] += yb * m4.x; yn1[1] += yb * m4.y; yn1[2] += yb * m4.z; yn1[3] += yb * m4.w;
            }
        }
        float4 zc0 = *(const float4*)&Zm[i0][j0];
        float4 zc1 = *(const float4*)&Zm[i0 + 1][j0];
        float4 yc0, yc1;
        if (!lastit) {
            yc0 = *(const float4*)&Ym[i0][j0];
            yc1 = *(const float4*)&Ym[i0 + 1][j0];
        }
        __syncwarp();
        *(float4*)&Zm[i0][j0] = make_float4(ca * zc0.x + cb * zn0[0], ca * zc0.y + cb * zn0[1],
                                            ca * zc0.z + cb * zn0[2], ca * zc0.w + cb * zn0[3]);
        *(float4*)&Zm[i0 + 1][j0] = make_float4(ca * zc1.x + cb * zn1[0], ca * zc1.y + cb * zn1[1],
                                                ca * zc1.z + cb * zn1[2], ca * zc1.w + cb * zn1[3]);
        if (!lastit) {
            *(float4*)&Ym[i0][j0] = make_float4(ca * yc0.x + cb * yn0[0], ca * yc0.y + cb * yn0[1],
                                                ca * yc0.z + cb * yn0[2], ca * yc0.w + cb * yn0[3]);
            *(float4*)&Ym[i0 + 1][j0] = make_float4(ca * yc1.x + cb * yn1[0], ca * yc1.y + cb * yn1[1],
                                                    ca * yc1.z + cb * yn1[2], ca * yc1.w + cb * yn1[3]);
        }
        __syncwarp();
    }

    // U = A * Z * s^(-1/2); own A rows come from registers
    float isq = rsqrtf(rs);
    float u0[16], u1[16];
#pragma unroll
    for (int c = 0; c < 16; c++) { u0[c] = 0.f; u1[c] = 0.f; }
#pragma unroll
    for (int k = 0; k < 16; k++) {
        float a0 = a0r[k], a1 = a1r[k];
#pragma unroll
        for (int cq = 0; cq < 4; cq++) {
            float4 z4 = *(const float4*)&Zm[k][cq * 4];
            u0[cq * 4 + 0] += a0 * z4.x; u0[cq * 4 + 1] += a0 * z4.y;
            u0[cq * 4 + 2] += a0 * z4.z; u0[cq * 4 + 3] += a0 * z4.w;
            u1[cq * 4 + 0] += a1 * z4.x; u1[cq * 4 + 1] += a1 * z4.y;
            u1[cq * 4 + 2] += a1 * z4.z; u1[cq * 4 + 3] += a1 * z4.w;
        }
    }
#pragma unroll
    for (int c = 0; c < 16; c++) { u0[c] *= isq; u1[c] *= isq; }

    // fp32 U out (lane's 128 contiguous bytes)
#pragma unroll
    for (int cq = 0; cq < 4; cq++) {
        *(float4*)(dst + r0 * 16 + cq * 4) =
            make_float4(u0[cq * 4], u0[cq * 4 + 1], u0[cq * 4 + 2], u0[cq * 4 + 3]);
        *(float4*)(dst + (r0 + 1) * 16 + cq * 4) =
            make_float4(u1[cq * 4], u1[cq * 4 + 1], u1[cq * 4 + 2], u1[cq * 4 + 3]);
    }

    // fp16 out direct (lane's 64 contiguous bytes; warp covers 2KB block)
    {
        __half* gh = g_hX[opar] + doff;
        uint32_t p[8];
#pragma unroll
        for (int cq = 0; cq < 8; cq++) {
            __half2 h2;
            h2.x = __float2half_rn(u0[2 * cq]);
            h2.y = __float2half_rn(u0[2 * cq + 1]);
            p[cq] = *(uint32_t*)&h2;
        }
        *(uint4*)(gh + r0 * 16)     = make_uint4(p[0], p[1], p[2], p[3]);
        *(uint4*)(gh + r0 * 16 + 8) = make_uint4(p[4], p[5], p[6], p[7]);
#pragma unroll
        for (int cq = 0; cq < 8; cq++) {
            __half2 h2;
            h2.x = __float2half_rn(u1[2 * cq]);
            h2.y = __float2half_rn(u1[2 * cq + 1]);
            p[cq] = *(uint32_t*)&h2;
        }
        *(uint4*)(gh + (r0 + 1) * 16)     = make_uint4(p[0], p[1], p[2], p[3]);
        *(uint4*)(gh + (r0 + 1) * 16 + 8) = make_uint4(p[4], p[5], p[6], p[7]);
    }
}

// ---------------- X_transformed transpose ------------------------------------
__global__ void xt_kernel(float* __restrict__ out) {
    __shared__ float tile[256][18];
    int base = blockIdx.x * 256;
    int tid = threadIdx.x;
#pragma unroll
    for (int l = 0; l < 17; l++)
        tile[tid][l] = g_xt[(size_t)l * PLANE + base + tid];
    __syncthreads();
    float* o = out + (size_t)base * 17;
    for (int i = tid; i < 256 * 17; i += 256)
        o[i] = tile[i / 17][i % 17];
}

// ---------------- reconstruct + classify + softmax ----------------------------
__global__ __launch_bounds__(128) void classify_kernel(
    const float* __restrict__ Wc, const float* __restrict__ bc,
    float* __restrict__ out, int off_log)
{
    __shared__ float sU[1024], sS[256], sV[1024], sT[1024];
    __shared__ float sZ[4096];
    __shared__ float red[10 * 136];
    __shared__ float slog[10];

    int b = blockIdx.x, tid = threadIdx.x;
    const float* base = g_xt + (size_t)16 * PLANE + (size_t)b * 3 * 1024;

    for (int i = tid; i < 1024; i += 128) { sU[i] = base[i]; sV[i] = base[2048 + i]; }
    for (int i = tid; i < 256; i += 128) sS[i] = base[1024 + i];
    __syncthreads();

    for (int e = tid; e < 1024; e += 128) {
        int r = e >> 4, c = e & 15;
        float sum = 0.f;
#pragma unroll
        for (int k = 0; k < 16; k++) sum += sU[r * 16 + k] * sS[k * 16 + c];
        sT[e] = sum;
    }
    __syncthreads();

    for (int e = tid; e < 4096; e += 128) {
        int r = e >> 6, qn = e & 63;
        float sum = 0.f;
#pragma unroll
        for (int c = 0; c < 16; c++) sum += sT[r * 16 + c] * sV[qn * 16 + c];
        sZ[e] = sum;
    }
    __syncthreads();

    float acc[10];
#pragma unroll
    for (int n = 0; n < 10; n++) acc[n] = 0.f;
    for (int e = tid; e < 4096; e += 128) {
        float z = sZ[e];
#pragma unroll
        for (int n = 0; n < 10; n++) acc[n] += z * Wc[n * 4096 + e];
    }
#pragma unroll
    for (int n = 0; n < 10; n++) red[n * 136 + tid] = acc[n];
    __syncthreads();
    if (tid < 10) {
        float s = bc[tid];
        for (int j = 0; j < 128; j++) s += red[tid * 136 + j];
        slog[tid] = s;
    }
    __syncthreads();
    if (tid == 0) {
        float mx = slog[0];
        for (int n = 1; n < 10; n++) mx = fmaxf(mx, slog[n]);
        float ex[10]; float se = 0.f;
        for (int n = 0; n < 10; n++) { ex[n] = expf(slog[n] - mx); se += ex[n]; }
        float inv = 1.f / se;
        for (int n = 0; n < 10; n++) {
            out[b * 10 + n] = ex[n] * inv;
            if (off_log >= 0) out[off_log + b * 10 + n] = slog[n];
        }
    }
}

// ---------------- launch ------------------------------------------------------
extern "C" void kernel_launch(void* const* d_in, const int* in_sizes, int n_in,
                              void* d_out, int out_size) {
    const float* X  = (const float*)d_in[0];
    const float* h  = (const float*)d_in[1];
    const float* W0 = (const float*)d_in[2];
    const float* Ws = (const float*)d_in[3];
    const float* bs = (const float*)d_in[4];
    const float* Wc = (const float*)d_in[5];
    const float* bc = (const float*)d_in[6];
    float* out = (float*)d_out;

    int off_log = -1, off_xt = -1;
    if (out_size >= 10240 + 10240 + 53477376) { off_log = 10240; off_xt = 20480; }
    else if (out_size == 10240 + 53477376)    { off_xt = 10240; }
    else if (out_size >= 20480)               { off_log = 10240; }

    cudaFuncSetAttribute(tgemm_kernel, cudaFuncAttributeMaxDynamicSharedMemorySize,
                         SMEM_TOTAL_G);

    wconv_kernel<<<WELEMS / 256, 256>>>(W0, Ws);
    prep_kernel<<<PLANE / 256, 256>>>(X);

    tgemm_kernel<<<256, 256, SMEM_TOTAL_G>>>(nullptr, h, 0);
    polar_kernel<<<512, 128>>>(0, 4, 5, 2.4f, -1.4f, 1);   // layer 0: 4 agg + 5 classic
    for (int l = 1; l <= 16; l++) {
        tgemm_kernel<<<256, 256, SMEM_TOTAL_G>>>(bs + (size_t)(l - 1) * 1024, h, l);
        polar_kernel<<<512, 128>>>(l, 1, 2, 1.9f, -0.9f, (l + 1) & 1);
    }

    if (off_xt >= 0)
        xt_kernel<<<PLANE / 256, 256>>>(out + off_xt);
    classify_kernel<<<1024, 128>>>(Wc, bc, out, off_log);
}

// round 13
// speedup vs baseline: 1.5321x; 1.0045x over previous
#include <cuda_runtime.h>
#include <cuda_fp16.h>
#include <math.h>
#include <stdint.h>

#define PLANE 3145728            // 3072 * 1024
#define WELEMS 17825792          // 17 * 1024 * 1024

// ---------------- device scratch --------------------------------------------
__device__ float g_Y[PLANE];                 // pre-projection Y of current layer
__device__ float g_xt[17 * PLANE];           // xs[l] planes (fp32)
__device__ __half g_hX[2][PLANE];            // ping-pong fp16 X
__device__ __half g_hW[WELEMS];              // fp16 weights (W0 at 0, Ws at 1..16)

// ---------------- helpers -----------------------------------------------------
typedef unsigned long long u64p;

static __device__ __forceinline__ uint32_t smem_u32(const void* p) {
    return (uint32_t)__cvta_generic_to_shared(p);
}
static __device__ __forceinline__ void ldsm4(uint32_t* r, uint32_t addr) {
    asm volatile("ldmatrix.sync.aligned.m8n8.x4.shared.b16 {%0,%1,%2,%3}, [%4];"
        : "=r"(r[0]), "=r"(r[1]), "=r"(r[2]), "=r"(r[3]) : "r"(addr));
}
static __device__ __forceinline__ void mma16816(float* c, const uint32_t* a,
                                                uint32_t b0, uint32_t b1) {
    asm volatile("mma.sync.aligned.m16n8k16.row.col.f32.f16.f16.f32 "
        "{%0,%1,%2,%3}, {%4,%5,%6,%7}, {%8,%9}, {%0,%1,%2,%3};"
        : "+f"(c[0]), "+f"(c[1]), "+f"(c[2]), "+f"(c[3])
        : "r"(a[0]), "r"(a[1]), "r"(a[2]), "r"(a[3]), "r"(b0), "r"(b1));
}
static __device__ __forceinline__ u64p pk2(float x, float y) {
    u64p r; asm("mov.b64 %0, {%1,%2};" : "=l"(r) : "f"(x), "f"(y)); return r;
}
static __device__ __forceinline__ void upk2(u64p v, float& x, float& y) {
    asm("mov.b64 {%0,%1}, %2;" : "=f"(x), "=f"(y) : "l"(v));
}
static __device__ __forceinline__ u64p fma2(u64p a, u64p b, u64p c) {
    u64p d; asm("fma.rn.f32x2 %0, %1, %2, %3;" : "=l"(d) : "l"(a), "l"(b), "l"(c));
    return d;
}
static __device__ __forceinline__ u64p mul2(u64p a, u64p b) {
    u64p d; asm("mul.rn.f32x2 %0, %1, %2;" : "=l"(d) : "l"(a), "l"(b));
    return d;
}

// ---------------- weight conversion (fp16) -----------------------------------
__global__ void wconv_kernel(const float* __restrict__ W0, const float* __restrict__ Ws) {
    size_t i = (size_t)blockIdx.x * 256 + threadIdx.x;
    if (i >= (size_t)WELEMS) return;
    float v = (i < 1048576) ? W0[i] : Ws[i - 1048576];
    g_hW[i] = __float2half_rn(v);
}

// ---------------- prep: fp16 of input (ch2 transposed) -----------------------
__global__ void prep_kernel(const float* __restrict__ Xin) {
    int idx = blockIdx.x * 256 + threadIdx.x;
    if (idx >= PLANE) return;
    int d  = idx & 1023;
    int bc = idx >> 10;
    int c  = bc % 3;
    float v;
    if (c == 2) {
        int b = bc / 3;
        int dim = d >> 4, k = d & 15;
        v = Xin[((size_t)(b * 3 + 2)) * 1024 + k * 64 + dim];
    } else {
        v = Xin[idx];
    }
    g_hX[0][idx] = __float2half_rn(v);
}

// ---------------- fp16 mma.sync GEMM + fused epilogue ------------------------
// Tile 96x128 (256 CTAs), K-chunk 32, 3-stage cp.async, 8 warps (2M x 4N).
#define MAT_STRIDE_B 80                  // bytes per smem row (pad, conflict-free)
#define A_BYTES (96 * MAT_STRIDE_B)      // 7680
#define B_BYTES (128 * MAT_STRIDE_B)     // 10240
#define STAGE_BYTES (A_BYTES + B_BYTES)  // 17920
#define SMEM_TOTAL_G (3 * STAGE_BYTES)   // 53760

__global__ __launch_bounds__(256, 2) void tgemm_kernel(
    const float* __restrict__ bias, const float* __restrict__ hp, int layer)
{
    extern __shared__ __align__(16) char smem[];
    uint32_t sb = smem_u32(smem);

    int tid = threadIdx.x;
    int wid = tid >> 5, lane = tid & 31;
    int bx = blockIdx.x;
    int m0 = (bx >> 3) * 96;
    int n0 = (bx & 7) * 128;

    int par = layer & 1;
    const __half* srcA = g_hX[par] + (size_t)m0 * 1024;
    const __half* srcB = g_hW + (size_t)layer * 1048576 + (size_t)n0 * 1024;

    float acc[3][4][4];
#pragma unroll
    for (int i = 0; i < 3; i++)
#pragma unroll
        for (int j = 0; j < 4; j++)
#pragma unroll
            for (int k = 0; k < 4; k++) acc[i][j][k] = 0.f;

    auto issue = [&](int c, int st) {
#pragma unroll
        for (int u = 0; u < 4; u++) {
            int unit = tid + u * 256;        // 0..1023, use 0..895
            if (unit < 896) {
                uint32_t dst;
                const __half* gp;
                if (unit < 384) {            // A: 96 rows x 4 segs
                    int row = unit >> 2, seg = unit & 3;
                    dst = sb + st * STAGE_BYTES + row * MAT_STRIDE_B + seg * 16;
                    gp = srcA + (size_t)row * 1024 + c * 32 + seg * 8;
                } else {                     // B: 128 rows x 4 segs
                    int t = unit - 384;
                    int row = t >> 2, seg = t & 3;
                    dst = sb + st * STAGE_BYTES + A_BYTES + row * MAT_STRIDE_B + seg * 16;
                    gp = srcB + (size_t)row * 1024 + c * 32 + seg * 8;
                }
                asm volatile("cp.async.cg.shared.global [%0], [%1], 16;"
                    :: "r"(dst), "l"(gp));
            }
        }
        asm volatile("cp.async.commit_group;" ::: "memory");
    };

    issue(0, 0);
    issue(1, 1);

    int mw = (wid >> 2) * 48, nw = (wid & 3) * 32;
    int lrow = (lane & 7) + ((lane >> 3) & 1) * 8;
    int lcolB = ((lane >> 4) * 8) * 2;

    for (int c = 0; c < 32; c++) {
        int st = c % 3;
        if (c < 31) {
            asm volatile("cp.async.wait_group 1;" ::: "memory");
        } else {
            asm volatile("cp.async.wait_group 0;" ::: "memory");
        }
        __syncthreads();
        if (c + 2 < 32) issue(c + 2, (c + 2) % 3);

        uint32_t base = sb + st * STAGE_BYTES;
#pragma unroll
        for (int ks = 0; ks < 2; ks++) {
            int colb = ks * 32 + lcolB;
            uint32_t bh[2][4];
#pragma unroll
            for (int nb = 0; nb < 2; nb++)
                ldsm4(bh[nb], base + A_BYTES +
                              (nw + nb * 16 + lrow) * MAT_STRIDE_B + colb);
#pragma unroll
            for (int ma = 0; ma < 3; ma++) {
                uint32_t ah[4];
                ldsm4(ah, base + (mw + ma * 16 + lrow) * MAT_STRIDE_B + colb);
#pragma unroll
                for (int na = 0; na < 4; na++) {
                    int nb = na >> 1, hi = na & 1;
                    mma16816(acc[ma][na], ah, bh[nb][hi], bh[nb][2 + hi]);
                }
            }
        }
    }

    // ---- fused epilogue
    float hv = 0.f;
    const float* Xprev = nullptr;
    if (layer > 0) { hv = *hp; Xprev = g_xt + (size_t)(layer - 1) * PLANE; }
    float* PL = g_xt + (size_t)layer * PLANE;
    int opar = (layer + 1) & 1;
    int g = lane >> 2, t2 = (lane & 3) * 2;

#pragma unroll
    for (int ma = 0; ma < 3; ma++) {
#pragma unroll
        for (int na = 0; na < 4; na++) {
            int n = n0 + nw + na * 8 + t2;
            float2 b2 = make_float2(0.f, 0.f);
            if (layer > 0) b2 = *(const float2*)(bias + n);
#pragma unroll
            for (int hh = 0; hh < 2; hh++) {
                int m = m0 + mw + ma * 16 + g + hh * 8;
                float cx = acc[ma][na][hh * 2], cy = acc[ma][na][hh * 2 + 1];
                float2 y;
                if (layer > 0) {
                    float2 xo = *(const float2*)(Xprev + (size_t)m * 1024 + n);
                    y.x = xo.x + hv * fmaxf(cx + b2.x, 0.f);
                    y.y = xo.y + hv * fmaxf(cy + b2.y, 0.f);
                } else {
                    y.x = cx; y.y = cy;
                }
                if (m % 3 == 1) {          // S channel: no projection
                    *(float2*)(PL + (size_t)m * 1024 + n) = y;
                    __half2 h2;
                    h2.x = __float2half_rn(y.x);
                    h2.y = __float2half_rn(y.y);
                    *(__half2*)(&g_hX[opar][(size_t)m * 1024 + n]) = h2;
                } else {                   // U/V channels: polar input only
                    *(float2*)(g_Y + (size_t)m * 1024 + n) = y;
                }
            }
        }
    }
}

// ---------------- polar projection (NS with packed f32x2 FMAs) ---------------
// R12 structure, inner matmuls rewritten with fma.rn.f32x2:
//  - Gram packed along row pairs (contiguous in col-major A -> free packing)
//  - NS matmuls + U packed along column pairs (float4/ull2 loads give operands)
#define PNW 4
__global__ __launch_bounds__(128) void polar_kernel(int plane, int nspecial,
                                                    int nclassic, float ca_s,
                                                    float cb_s, int opar) {
    __shared__ float AsP[PNW][16][68];
    __shared__ float MsP[PNW][3][16][20];

    int w = threadIdx.x >> 5, lane = threadIdx.x & 31;
    int idx = blockIdx.x * PNW + w;
    int b = idx >> 1, ch = (idx & 1) * 2;

    const float* src = g_Y + (size_t)(b * 3 + ch) * 1024;
    size_t doff = (size_t)(b * 3 + ch) * 1024;
    float* dst = g_xt + (size_t)plane * PLANE + doff;

    float (*A)[68]  = AsP[w];
    float (*Ym)[20] = MsP[w][0];
    float (*Zm)[20] = MsP[w][1];
    float (*Tm)[20] = MsP[w][2];

    int r0 = lane * 2;
    float a0r[16], a1r[16];            // own two A rows kept in registers
#pragma unroll
    for (int qq = 0; qq < 4; qq++) {
        float4 v0 = *(const float4*)(src + r0 * 16 + qq * 4);
        float4 v1 = *(const float4*)(src + (r0 + 1) * 16 + qq * 4);
        a0r[qq * 4 + 0] = v0.x; a0r[qq * 4 + 1] = v0.y;
        a0r[qq * 4 + 2] = v0.z; a0r[qq * 4 + 3] = v0.w;
        a1r[qq * 4 + 0] = v1.x; a1r[qq * 4 + 1] = v1.y;
        a1r[qq * 4 + 2] = v1.z; a1r[qq * 4 + 3] = v1.w;
        A[qq * 4 + 0][r0] = v0.x; A[qq * 4 + 1][r0] = v0.y;
        A[qq * 4 + 2][r0] = v0.z; A[qq * 4 + 3][r0] = v0.w;
        A[qq * 4 + 0][r0 + 1] = v1.x; A[qq * 4 + 1][r0 + 1] = v1.y;
        A[qq * 4 + 2][r0 + 1] = v1.z; A[qq * 4 + 3][r0 + 1] = v1.w;
    }
    __syncwarp();

    int i0 = (lane >> 2) * 2, j0 = (lane & 3) * 4;

    // ---- Gram: packed along r-pairs (ulonglong2 smem loads = free packing)
    u64p gp0[4], gp1[4];
#pragma unroll
    for (int t = 0; t < 4; t++) { gp0[t] = 0ull; gp1[t] = 0ull; }
#pragma unroll
    for (int r = 0; r < 64; r += 4) {
        ulonglong2 a0 = *(const ulonglong2*)&A[i0][r];
        ulonglong2 a1 = *(const ulonglong2*)&A[i0 + 1][r];
#pragma unroll
        for (int t = 0; t < 4; t++) {
            ulonglong2 aj = *(const ulonglong2*)&A[j0 + t][r];
            gp0[t] = fma2(a0.x, aj.x, gp0[t]);
            gp0[t] = fma2(a0.y, aj.y, gp0[t]);
            gp1[t] = fma2(a1.x, aj.x, gp1[t]);
            gp1[t] = fma2(a1.y, aj.y, gp1[t]);
        }
    }
    float g0[4], g1[4];
#pragma unroll
    for (int t = 0; t < 4; t++) {
        float lo, hi;
        upk2(gp0[t], lo, hi); g0[t] = lo + hi;
        upk2(gp1[t], lo, hi); g1[t] = lo + hi;
    }
    *(float4*)&Ym[i0][j0]     = make_float4(g0[0], g0[1], g0[2], g0[3]);
    *(float4*)&Ym[i0 + 1][j0] = make_float4(g1[0], g1[1], g1[2], g1[3]);
    __syncwarp();

    float rs = 0.f;
    if (lane < 16) {
#pragma unroll
        for (int j = 0; j < 16; j++) rs += fabsf(Ym[lane][j]);
    }
#pragma unroll
    for (int off = 16; off; off >>= 1)
        rs = fmaxf(rs, __shfl_xor_sync(0xffffffffu, rs, off));
    float invs = 1.0f / rs;

#pragma unroll
    for (int t = 0; t < 4; t++) { g0[t] *= invs; g1[t] *= invs; }
    *(float4*)&Ym[i0][j0]     = make_float4(g0[0], g0[1], g0[2], g0[3]);
    *(float4*)&Ym[i0 + 1][j0] = make_float4(g1[0], g1[1], g1[2], g1[3]);
    __syncwarp();

    int ntot = nspecial + nclassic;

    // ---- iteration 0 (Z0 = I): S = Y*Y; Y1 = ca*Y + cb*S; Z1 = ca*I + cb*Y
    {
        float ca = (0 < nspecial) ? ca_s : 1.5f;
        float cb = (0 < nspecial) ? cb_s : -0.5f;
        u64p cap = pk2(ca, ca), cbp = pk2(cb, cb);
        u64p s0p[2] = {0ull, 0ull}, s1p[2] = {0ull, 0ull};
#pragma unroll
        for (int k = 0; k < 16; k++) {
            float ya = Ym[i0][k], yb = Ym[i0 + 1][k];
            u64p yap = pk2(ya, ya), ybp = pk2(yb, yb);
            ulonglong2 y2 = *(const ulonglong2*)&Ym[k][j0];
            s0p[0] = fma2(yap, y2.x, s0p[0]); s0p[1] = fma2(yap, y2.y, s0p[1]);
            s1p[0] = fma2(ybp, y2.x, s1p[0]); s1p[1] = fma2(ybp, y2.y, s1p[1]);
        }
        ulonglong2 yc0 = *(const ulonglong2*)&Ym[i0][j0];
        ulonglong2 yc1 = *(const ulonglong2*)&Ym[i0 + 1][j0];
        __syncwarp();
        ulonglong2 ny0, ny1;
        ny0.x = fma2(cbp, s0p[0], mul2(cap, yc0.x));
        ny0.y = fma2(cbp, s0p[1], mul2(cap, yc0.y));
        ny1.x = fma2(cbp, s1p[0], mul2(cap, yc1.x));
        ny1.y = fma2(cbp, s1p[1], mul2(cap, yc1.y));
        *(ulonglong2*)&Ym[i0][j0]     = ny0;
        *(ulonglong2*)&Ym[i0 + 1][j0] = ny1;
        // Z1 = ca*I + cb*Y0 (scalar, from yc registers)
        float y00, y01, y02, y03, y10, y11, y12, y13;
        upk2(yc0.x, y00, y01); upk2(yc0.y, y02, y03);
        upk2(yc1.x, y10, y11); upk2(yc1.y, y12, y13);
        *(float4*)&Zm[i0][j0] = make_float4(
            (i0 == j0 ? ca : 0.f) + cb * y00, (i0 == j0 + 1 ? ca : 0.f) + cb * y01,
            (i0 == j0 + 2 ? ca : 0.f) + cb * y02, (i0 == j0 + 3 ? ca : 0.f) + cb * y03);
        *(float4*)&Zm[i0 + 1][j0] = make_float4(
            (i0 + 1 == j0 ? ca : 0.f) + cb * y10, (i0 + 1 == j0 + 1 ? ca : 0.f) + cb * y11,
            (i0 + 1 == j0 + 2 ? ca : 0.f) + cb * y12, (i0 + 1 == j0 + 3 ? ca : 0.f) + cb * y13);
        __syncwarp();
    }

    for (int it = 1; it < ntot; it++) {
        float ca = (it < nspecial) ? ca_s : 1.5f;
        float cb = (it < nspecial) ? cb_s : -0.5f;
        bool lastit = (it == ntot - 1);
        u64p cap = pk2(ca, ca), cbp = pk2(cb, cb);

        // M = Z*Y -> Tm (packed along columns)
        {
            u64p t0p[2] = {0ull, 0ull}, t1p[2] = {0ull, 0ull};
#pragma unroll
            for (int k = 0; k < 16; k++) {
                float z0 = Zm[i0][k], z1 = Zm[i0 + 1][k];
                u64p z0p = pk2(z0, z0), z1p = pk2(z1, z1);
                ulonglong2 y2 = *(const ulonglong2*)&Ym[k][j0];
                t0p[0] = fma2(z0p, y2.x, t0p[0]); t0p[1] = fma2(z0p, y2.y, t0p[1]);
                t1p[0] = fma2(z1p, y2.x, t1p[0]); t1p[1] = fma2(z1p, y2.y, t1p[1]);
            }
            ulonglong2 tw0, tw1;
            tw0.x = t0p[0]; tw0.y = t0p[1];
            tw1.x = t1p[0]; tw1.y = t1p[1];
            *(ulonglong2*)&Tm[i0][j0]     = tw0;
            *(ulonglong2*)&Tm[i0 + 1][j0] = tw1;
        }
        __syncwarp();

        // Znew = ca*Z + cb*(Z*M); Ynew = ca*Y + cb*(Y*M) (skip Y on last)
        u64p zn0p[2] = {0ull, 0ull}, zn1p[2] = {0ull, 0ull};
        u64p yn0p[2] = {0ull, 0ull}, yn1p[2] = {0ull, 0ull};
#pragma unroll
        for (int k = 0; k < 16; k++) {
            ulonglong2 m2 = *(const ulonglong2*)&Tm[k][j0];
            float za = Zm[i0][k], zb = Zm[i0 + 1][k];
            u64p zap = pk2(za, za), zbp = pk2(zb, zb);
            zn0p[0] = fma2(zap, m2.x, zn0p[0]); zn0p[1] = fma2(zap, m2.y, zn0p[1]);
            zn1p[0] = fma2(zbp, m2.x, zn1p[0]); zn1p[1] = fma2(zbp, m2.y, zn1p[1]);
            if (!lastit) {
                float ya = Ym[i0][k], yb = Ym[i0 + 1][k];
                u64p yap = pk2(ya, ya), ybp = pk2(yb, yb);
                yn0p[0] = fma2(yap, m2.x, yn0p[0]); yn0p[1] = fma2(yap, m2.y, yn0p[1]);
                yn1p[0] = fma2(ybp, m2.x, yn1p[0]); yn1p[1] = fma2(ybp, m2.y, yn1p[1]);
            }
        }
        ulonglong2 zc0 = *(const ulonglong2*)&Zm[i0][j0];
        ulonglong2 zc1 = *(const ulonglong2*)&Zm[i0 + 1][j0];
        ulonglong2 yc0, yc1;
        if (!lastit) {
            yc0 = *(const ulonglong2*)&Ym[i0][j0];
            yc1 = *(const ulonglong2*)&Ym[i0 + 1][j0];
        }
        __syncwarp();
        ulonglong2 o;
        o.x = fma2(cbp, zn0p[0], mul2(cap, zc0.x));
        o.y = fma2(cbp, zn0p[1], mul2(cap, zc0.y));
        *(ulonglong2*)&Zm[i0][j0] = o;
        o.x = fma2(cbp, zn1p[0], mul2(cap, zc1.x));
        o.y = fma2(cbp, zn1p[1], mul2(cap, zc1.y));
        *(ulonglong2*)&Zm[i0 + 1][j0] = o;
        if (!lastit) {
            o.x = fma2(cbp, yn0p[0], mul2(cap, yc0.x));
            o.y = fma2(cbp, yn0p[1], mul2(cap, yc0.y));
            *(ulonglong2*)&Ym[i0][j0] = o;
            o.x = fma2(cbp, yn1p[0], mul2(cap, yc1.x));
            o.y = fma2(cbp, yn1p[1], mul2(cap, yc1.y));
            *(ulonglong2*)&Ym[i0 + 1][j0] = o;
        }
        __syncwarp();
    }

    // ---- U = A * Z * s^(-1/2); packed along column pairs
    float isq = rsqrtf(rs);
    u64p isqp = pk2(isq, isq);
    u64p u0p[8], u1p[8];
#pragma unroll
    for (int j = 0; j < 8; j++) { u0p[j] = 0ull; u1p[j] = 0ull; }
#pragma unroll
    for (int k = 0; k < 16; k++) {
        u64p a0p = pk2(a0r[k], a0r[k]);
        u64p a1p = pk2(a1r[k], a1r[k]);
#pragma unroll
        for (int cq = 0; cq < 4; cq++) {
            ulonglong2 z2 = *(const ulonglong2*)&Zm[k][cq * 4];
            u0p[cq * 2]     = fma2(a0p, z2.x, u0p[cq * 2]);
            u0p[cq * 2 + 1] = fma2(a0p, z2.y, u0p[cq * 2 + 1]);
            u1p[cq * 2]     = fma2(a1p, z2.x, u1p[cq * 2]);
            u1p[cq * 2 + 1] = fma2(a1p, z2.y, u1p[cq * 2 + 1]);
        }
    }
#pragma unroll
    for (int j = 0; j < 8; j++) {
        u0p[j] = mul2(u0p[j], isqp);
        u1p[j] = mul2(u1p[j], isqp);
    }

    // fp32 U out (lane's 128 contiguous bytes)
#pragma unroll
    for (int cq = 0; cq < 4; cq++) {
        ulonglong2 s0, s1;
        s0.x = u0p[cq * 2]; s0.y = u0p[cq * 2 + 1];
        s1.x = u1p[cq * 2]; s1.y = u1p[cq * 2 + 1];
        *(ulonglong2*)(dst + r0 * 16 + cq * 4)       = s0;
        *(ulonglong2*)(dst + (r0 + 1) * 16 + cq * 4) = s1;
    }

    // fp16 out direct (lane's 64 contiguous bytes; warp covers 2KB block)
    {
        __half* gh = g_hX[opar] + doff;
        uint32_t p[8];
#pragma unroll
        for (int j = 0; j < 8; j++) {
            float lo, hi;
            upk2(u0p[j], lo, hi);
            __half2 h2;
            h2.x = __float2half_rn(lo);
            h2.y = __float2half_rn(hi);
            p[j] = *(uint32_t*)&h2;
        }
        *(uint4*)(gh + r0 * 16)     = make_uint4(p[0], p[1], p[2], p[3]);
        *(uint4*)(gh + r0 * 16 + 8) = make_uint4(p[4], p[5], p[6], p[7]);
#pragma unroll
        for (int j = 0; j < 8; j++) {
            float lo, hi;
            upk2(u1p[j], lo, hi);
            __half2 h2;
            h2.x = __float2half_rn(lo);
            h2.y = __float2half_rn(hi);
            p[j] = *(uint32_t*)&h2;
        }
        *(uint4*)(gh + (r0 + 1) * 16)     = make_uint4(p[0], p[1], p[2], p[3]);
        *(uint4*)(gh + (r0 + 1) * 16 + 8) = make_uint4(p[4], p[5], p[6], p[7]);
    }
}

// ---------------- X_transformed transpose ------------------------------------
__global__ void xt_kernel(float* __restrict__ out) {
    __shared__ float tile[256][18];
    int base = blockIdx.x * 256;
    int tid = threadIdx.x;
#pragma unroll
    for (int l = 0; l < 17; l++)
        tile[tid][l] = g_xt[(size_t)l * PLANE + base + tid];
    __syncthreads();
    float* o = out + (size_t)base * 17;
    for (int i = tid; i < 256 * 17; i += 256)
        o[i] = tile[i / 17][i % 17];
}

// ---------------- reconstruct + classify + softmax ----------------------------
__global__ __launch_bounds__(128) void classify_kernel(
    const float* __restrict__ Wc, const float* __restrict__ bc,
    float* __restrict__ out, int off_log)
{
    __shared__ float sU[1024], sS[256], sV[1024], sT[1024];
    __shared__ float sZ[4096];
    __shared__ float red[10 * 136];
    __shared__ float slog[10];

    int b = blockIdx.x, tid = threadIdx.x;
    const float* base = g_xt + (size_t)16 * PLANE + (size_t)b * 3 * 1024;

    for (int i = tid; i < 1024; i += 128) { sU[i] = base[i]; sV[i] = base[2048 + i]; }
    for (int i = tid; i < 256; i += 128) sS[i] = base[1024 + i];
    __syncthreads();

    for (int e = tid; e < 1024; e += 128) {
        int r = e >> 4, c = e & 15;
        float sum = 0.f;
#pragma unroll
        for (int k = 0; k < 16; k++) sum += sU[r * 16 + k] * sS[k * 16 + c];
        sT[e] = sum;
    }
    __syncthreads();

    for (int e = tid; e < 4096; e += 128) {
        int r = e >> 6, qn = e & 63;
        float sum = 0.f;
#pragma unroll
        for (int c = 0; c < 16; c++) sum += sT[r * 16 + c] * sV[qn * 16 + c];
        sZ[e] = sum;
    }
    __syncthreads();

    float acc[10];
#pragma unroll
    for (int n = 0; n < 10; n++) acc[n] = 0.f;
    for (int e = tid; e < 4096; e += 128) {
        float z = sZ[e];
#pragma unroll
        for (int n = 0; n < 10; n++) acc[n] += z * Wc[n * 4096 + e];
    }
#pragma unroll
    for (int n = 0; n < 10; n++) red[n * 136 + tid] = acc[n];
    __syncthreads();
    if (tid < 10) {
        float s = bc[tid];
        for (int j = 0; j < 128; j++) s += red[tid * 136 + j];
        slog[tid] = s;
    }
    __syncthreads();
    if (tid == 0) {
        float mx = slog[0];
        for (int n = 1; n < 10; n++) mx = fmaxf(mx, slog[n]);
        float ex[10]; float se = 0.f;
        for (int n = 0; n < 10; n++) { ex[n] = expf(slog[n] - mx); se += ex[n]; }
        float inv = 1.f / se;
        for (int n = 0; n < 10; n++) {
            out[b * 10 + n] = ex[n] * inv;
            if (off_log >= 0) out[off_log + b * 10 + n] = slog[n];
        }
    }
}

// ---------------- launch ------------------------------------------------------
extern "C" void kernel_launch(void* const* d_in, const int* in_sizes, int n_in,
                              void* d_out, int out_size) {
    const float* X  = (const float*)d_in[0];
    const float* h  = (const float*)d_in[1];
    const float* W0 = (const float*)d_in[2];
    const float* Ws = (const float*)d_in[3];
    const float* bs = (const float*)d_in[4];
    const float* Wc = (const float*)d_in[5];
    const float* bc = (const float*)d_in[6];
    float* out = (float*)d_out;

    int off_log = -1, off_xt = -1;
    if (out_size >= 10240 + 10240 + 53477376) { off_log = 10240; off_xt = 20480; }
    else if (out_size == 10240 + 53477376)    { off_xt = 10240; }
    else if (out_size >= 20480)               { off_log = 10240; }

    cudaFuncSetAttribute(tgemm_kernel, cudaFuncAttributeMaxDynamicSharedMemorySize,
                         SMEM_TOTAL_G);

    wconv_kernel<<<WELEMS / 256, 256>>>(W0, Ws);
    prep_kernel<<<PLANE / 256, 256>>>(X);

    tgemm_kernel<<<256, 256, SMEM_TOTAL_G>>>(nullptr, h, 0);
    polar_kernel<<<512, 128>>>(0, 4, 5, 2.4f, -1.4f, 1);   // layer 0: 4 agg + 5 classic
    for (int l = 1; l <= 16; l++) {
        tgemm_kernel<<<256, 256, SMEM_TOTAL_G>>>(bs + (size_t)(l - 1) * 1024, h, l);
        polar_kernel<<<512, 128>>>(l, 1, 2, 1.9f, -0.9f, (l + 1) & 1);
    }

    if (off_xt >= 0)
        xt_kernel<<<PLANE / 256, 256>>>(out + off_xt);
    classify_kernel<<<1024, 128>>>(Wc, bc, out, off_log);
}

// round 14
// speedup vs baseline: 1.5473x; 1.0099x over previous
#include <cuda_runtime.h>
#include <cuda_fp16.h>
#include <math.h>
#include <stdint.h>

#define PLANE 3145728            // 3072 * 1024
#define WELEMS 17825792          // 17 * 1024 * 1024

// ---------------- device scratch --------------------------------------------
__device__ float g_Y[PLANE];                 // pre-projection Y of current layer
__device__ float g_xt[17 * PLANE];           // xs[l] planes (fp32)
__device__ __half g_hX[2][PLANE];            // ping-pong fp16 X
__device__ __half g_hW[WELEMS];              // fp16 weights (W0 at 0, Ws at 1..16)

// ---------------- helpers -----------------------------------------------------
typedef unsigned long long u64p;

static __device__ __forceinline__ uint32_t smem_u32(const void* p) {
    return (uint32_t)__cvta_generic_to_shared(p);
}
static __device__ __forceinline__ void ldsm4(uint32_t* r, uint32_t addr) {
    asm volatile("ldmatrix.sync.aligned.m8n8.x4.shared.b16 {%0,%1,%2,%3}, [%4];"
        : "=r"(r[0]), "=r"(r[1]), "=r"(r[2]), "=r"(r[3]) : "r"(addr));
}
static __device__ __forceinline__ void mma16816(float* c, const uint32_t* a,
                                                uint32_t b0, uint32_t b1) {
    asm volatile("mma.sync.aligned.m16n8k16.row.col.f32.f16.f16.f32 "
        "{%0,%1,%2,%3}, {%4,%5,%6,%7}, {%8,%9}, {%0,%1,%2,%3};"
        : "+f"(c[0]), "+f"(c[1]), "+f"(c[2]), "+f"(c[3])
        : "r"(a[0]), "r"(a[1]), "r"(a[2]), "r"(a[3]), "r"(b0), "r"(b1));
}
static __device__ __forceinline__ u64p pk2(float x, float y) {
    u64p r; asm("mov.b64 %0, {%1,%2};" : "=l"(r) : "f"(x), "f"(y)); return r;
}
static __device__ __forceinline__ void upk2(u64p v, float& x, float& y) {
    asm("mov.b64 {%0,%1}, %2;" : "=f"(x), "=f"(y) : "l"(v));
}
static __device__ __forceinline__ u64p fma2(u64p a, u64p b, u64p c) {
    u64p d; asm("fma.rn.f32x2 %0, %1, %2, %3;" : "=l"(d) : "l"(a), "l"(b), "l"(c));
    return d;
}
static __device__ __forceinline__ u64p mul2(u64p a, u64p b) {
    u64p d; asm("mul.rn.f32x2 %0, %1, %2;" : "=l"(d) : "l"(a), "l"(b));
    return d;
}

// ---------------- weight conversion (fp16) -----------------------------------
__global__ void wconv_kernel(const float* __restrict__ W0, const float* __restrict__ Ws) {
    size_t i = (size_t)blockIdx.x * 256 + threadIdx.x;
    if (i >= (size_t)WELEMS) return;
    float v = (i < 1048576) ? W0[i] : Ws[i - 1048576];
    g_hW[i] = __float2half_rn(v);
}

// ---------------- prep: fp16 of input (ch2 transposed) -----------------------
__global__ void prep_kernel(const float* __restrict__ Xin) {
    int idx = blockIdx.x * 256 + threadIdx.x;
    if (idx >= PLANE) return;
    int d  = idx & 1023;
    int bc = idx >> 10;
    int c  = bc % 3;
    float v;
    if (c == 2) {
        int b = bc / 3;
        int dim = d >> 4, k = d & 15;
        v = Xin[((size_t)(b * 3 + 2)) * 1024 + k * 64 + dim];
    } else {
        v = Xin[idx];
    }
    g_hX[0][idx] = __float2half_rn(v);
}

// ---------------- fp16 mma.sync GEMM + fused epilogue ------------------------
// Tile 96x128 (256 CTAs), K-chunk 32, 3-stage cp.async, 8 warps (2M x 4N).
#define MAT_STRIDE_B 80                  // bytes per smem row (pad, conflict-free)
#define A_BYTES (96 * MAT_STRIDE_B)      // 7680
#define B_BYTES (128 * MAT_STRIDE_B)     // 10240
#define STAGE_BYTES (A_BYTES + B_BYTES)  // 17920
#define SMEM_TOTAL_G (3 * STAGE_BYTES)   // 53760

__global__ __launch_bounds__(256, 2) void tgemm_kernel(
    const float* __restrict__ bias, const float* __restrict__ hp, int layer)
{
    extern __shared__ __align__(16) char smem[];
    uint32_t sb = smem_u32(smem);

    int tid = threadIdx.x;
    int wid = tid >> 5, lane = tid & 31;
    int bx = blockIdx.x;
    int m0 = (bx >> 3) * 96;
    int n0 = (bx & 7) * 128;

    int par = layer & 1;
    const __half* srcA = g_hX[par] + (size_t)m0 * 1024;
    const __half* srcB = g_hW + (size_t)layer * 1048576 + (size_t)n0 * 1024;

    float acc[3][4][4];
#pragma unroll
    for (int i = 0; i < 3; i++)
#pragma unroll
        for (int j = 0; j < 4; j++)
#pragma unroll
            for (int k = 0; k < 4; k++) acc[i][j][k] = 0.f;

    auto issue = [&](int c, int st) {
#pragma unroll
        for (int u = 0; u < 4; u++) {
            int unit = tid + u * 256;        // 0..1023, use 0..895
            if (unit < 896) {
                uint32_t dst;
                const __half* gp;
                if (unit < 384) {            // A: 96 rows x 4 segs
                    int row = unit >> 2, seg = unit & 3;
                    dst = sb + st * STAGE_BYTES + row * MAT_STRIDE_B + seg * 16;
                    gp = srcA + (size_t)row * 1024 + c * 32 + seg * 8;
                } else {                     // B: 128 rows x 4 segs
                    int t = unit - 384;
                    int row = t >> 2, seg = t & 3;
                    dst = sb + st * STAGE_BYTES + A_BYTES + row * MAT_STRIDE_B + seg * 16;
                    gp = srcB + (size_t)row * 1024 + c * 32 + seg * 8;
                }
                asm volatile("cp.async.cg.shared.global [%0], [%1], 16;"
                    :: "r"(dst), "l"(gp));
            }
        }
        asm volatile("cp.async.commit_group;" ::: "memory");
    };

    issue(0, 0);
    issue(1, 1);

    int mw = (wid >> 2) * 48, nw = (wid & 3) * 32;
    int lrow = (lane & 7) + ((lane >> 3) & 1) * 8;
    int lcolB = ((lane >> 4) * 8) * 2;

    for (int c = 0; c < 32; c++) {
        int st = c % 3;
        if (c < 31) {
            asm volatile("cp.async.wait_group 1;" ::: "memory");
        } else {
            asm volatile("cp.async.wait_group 0;" ::: "memory");
        }
        __syncthreads();
        if (c + 2 < 32) issue(c + 2, (c + 2) % 3);

        uint32_t base = sb + st * STAGE_BYTES;
#pragma unroll
        for (int ks = 0; ks < 2; ks++) {
            int colb = ks * 32 + lcolB;
            uint32_t bh[2][4];
#pragma unroll
            for (int nb = 0; nb < 2; nb++)
                ldsm4(bh[nb], base + A_BYTES +
                              (nw + nb * 16 + lrow) * MAT_STRIDE_B + colb);
#pragma unroll
            for (int ma = 0; ma < 3; ma++) {
                uint32_t ah[4];
                ldsm4(ah, base + (mw + ma * 16 + lrow) * MAT_STRIDE_B + colb);
#pragma unroll
                for (int na = 0; na < 4; na++) {
                    int nb = na >> 1, hi = na & 1;
                    mma16816(acc[ma][na], ah, bh[nb][hi], bh[nb][2 + hi]);
                }
            }
        }
    }

    // ---- fused epilogue
    float hv = 0.f;
    const float* Xprev = nullptr;
    if (layer > 0) { hv = *hp; Xprev = g_xt + (size_t)(layer - 1) * PLANE; }
    float* PL = g_xt + (size_t)layer * PLANE;
    int opar = (layer + 1) & 1;
    int g = lane >> 2, t2 = (lane & 3) * 2;

#pragma unroll
    for (int ma = 0; ma < 3; ma++) {
#pragma unroll
        for (int na = 0; na < 4; na++) {
            int n = n0 + nw + na * 8 + t2;
            float2 b2 = make_float2(0.f, 0.f);
            if (layer > 0) b2 = *(const float2*)(bias + n);
#pragma unroll
            for (int hh = 0; hh < 2; hh++) {
                int m = m0 + mw + ma * 16 + g + hh * 8;
                float cx = acc[ma][na][hh * 2], cy = acc[ma][na][hh * 2 + 1];
                float2 y;
                if (layer > 0) {
                    float2 xo = *(const float2*)(Xprev + (size_t)m * 1024 + n);
                    y.x = xo.x + hv * fmaxf(cx + b2.x, 0.f);
                    y.y = xo.y + hv * fmaxf(cy + b2.y, 0.f);
                } else {
                    y.x = cx; y.y = cy;
                }
                if (m % 3 == 1) {          // S channel: no projection
                    *(float2*)(PL + (size_t)m * 1024 + n) = y;
                    __half2 h2;
                    h2.x = __float2half_rn(y.x);
                    h2.y = __float2half_rn(y.y);
                    *(__half2*)(&g_hX[opar][(size_t)m * 1024 + n]) = h2;
                } else {                   // U/V channels: polar input only
                    *(float2*)(g_Y + (size_t)m * 1024 + n) = y;
                }
            }
        }
    }
}

// ---------------- polar projection (NS, smem-op minimized) -------------------
// L1/LSU-bound kernel: packed f32x2 math + minimal smem instruction count.
//  - A transpose-store as float2 pairs (16 STS.64)
//  - inf-norm via register partials + 7 shuffles (no smem round trip)
//  - NS iterations cache Z/Y rows i0,i0+1 in registers (8 LDS.128 per matrix
//    per phase) instead of 32-64 scalar LDS broadcasts
//  - U phase reads A as float2 from smem
#define PNW 4
__global__ __launch_bounds__(128) void polar_kernel(int plane, int nspecial,
                                                    int nclassic, float ca_s,
                                                    float cb_s, int opar) {
    __shared__ float AsP[PNW][16][68];
    __shared__ float MsP[PNW][3][16][20];

    int w = threadIdx.x >> 5, lane = threadIdx.x & 31;
    int idx = blockIdx.x * PNW + w;
    int b = idx >> 1, ch = (idx & 1) * 2;

    const float* src = g_Y + (size_t)(b * 3 + ch) * 1024;
    size_t doff = (size_t)(b * 3 + ch) * 1024;
    float* dst = g_xt + (size_t)plane * PLANE + doff;

    float (*A)[68]  = AsP[w];
    float (*Ym)[20] = MsP[w][0];
    float (*Zm)[20] = MsP[w][1];
    float (*Tm)[20] = MsP[w][2];

    int r0 = lane * 2;
    // load A rows r0,r0+1 and transpose-store col-major as float2 (rows adjacent)
#pragma unroll
    for (int qq = 0; qq < 4; qq++) {
        float4 v0 = *(const float4*)(src + r0 * 16 + qq * 4);
        float4 v1 = *(const float4*)(src + (r0 + 1) * 16 + qq * 4);
        *(float2*)&A[qq * 4 + 0][r0] = make_float2(v0.x, v1.x);
        *(float2*)&A[qq * 4 + 1][r0] = make_float2(v0.y, v1.y);
        *(float2*)&A[qq * 4 + 2][r0] = make_float2(v0.z, v1.z);
        *(float2*)&A[qq * 4 + 3][r0] = make_float2(v0.w, v1.w);
    }
    __syncwarp();

    int i0 = (lane >> 2) * 2, j0 = (lane & 3) * 4;

    // ---- Gram: packed along r-pairs (ulonglong2 smem loads = free packing)
    u64p gp0[4], gp1[4];
#pragma unroll
    for (int t = 0; t < 4; t++) { gp0[t] = 0ull; gp1[t] = 0ull; }
#pragma unroll
    for (int r = 0; r < 64; r += 4) {
        ulonglong2 a0 = *(const ulonglong2*)&A[i0][r];
        ulonglong2 a1 = *(const ulonglong2*)&A[i0 + 1][r];
#pragma unroll
        for (int t = 0; t < 4; t++) {
            ulonglong2 aj = *(const ulonglong2*)&A[j0 + t][r];
            gp0[t] = fma2(a0.x, aj.x, gp0[t]);
            gp0[t] = fma2(a0.y, aj.y, gp0[t]);
            gp1[t] = fma2(a1.x, aj.x, gp1[t]);
            gp1[t] = fma2(a1.y, aj.y, gp1[t]);
        }
    }
    float g0[4], g1[4];
#pragma unroll
    for (int t = 0; t < 4; t++) {
        float lo, hi;
        upk2(gp0[t], lo, hi); g0[t] = lo + hi;
        upk2(gp1[t], lo, hi); g1[t] = lo + hi;
    }

    // ---- inf-norm from register partials (no smem)
    float rs0 = fabsf(g0[0]) + fabsf(g0[1]) + fabsf(g0[2]) + fabsf(g0[3]);
    float rs1 = fabsf(g1[0]) + fabsf(g1[1]) + fabsf(g1[2]) + fabsf(g1[3]);
    rs0 += __shfl_xor_sync(0xffffffffu, rs0, 1);
    rs0 += __shfl_xor_sync(0xffffffffu, rs0, 2);
    rs1 += __shfl_xor_sync(0xffffffffu, rs1, 1);
    rs1 += __shfl_xor_sync(0xffffffffu, rs1, 2);
    float rs = fmaxf(rs0, rs1);
    rs = fmaxf(rs, __shfl_xor_sync(0xffffffffu, rs, 4));
    rs = fmaxf(rs, __shfl_xor_sync(0xffffffffu, rs, 8));
    rs = fmaxf(rs, __shfl_xor_sync(0xffffffffu, rs, 16));
    float invs = 1.0f / rs;

#pragma unroll
    for (int t = 0; t < 4; t++) { g0[t] *= invs; g1[t] *= invs; }
    *(float4*)&Ym[i0][j0]     = make_float4(g0[0], g0[1], g0[2], g0[3]);
    *(float4*)&Ym[i0 + 1][j0] = make_float4(g1[0], g1[1], g1[2], g1[3]);
    __syncwarp();

    int ntot = nspecial + nclassic;

    // ---- iteration 0 (Z0 = I): S = Y*Y; Y1 = ca*Y + cb*S; Z1 = ca*I + cb*Y
    {
        float ca = (0 < nspecial) ? ca_s : 1.5f;
        float cb = (0 < nspecial) ? cb_s : -0.5f;
        u64p cap = pk2(ca, ca), cbp = pk2(cb, cb);
        // rows i0, i0+1 of Y into registers
        float yr0[16], yr1[16];
#pragma unroll
        for (int qq = 0; qq < 4; qq++) {
            float4 a = *(const float4*)&Ym[i0][qq * 4];
            float4 bqq = *(const float4*)&Ym[i0 + 1][qq * 4];
            yr0[qq * 4 + 0] = a.x; yr0[qq * 4 + 1] = a.y;
            yr0[qq * 4 + 2] = a.z; yr0[qq * 4 + 3] = a.w;
            yr1[qq * 4 + 0] = bqq.x; yr1[qq * 4 + 1] = bqq.y;
            yr1[qq * 4 + 2] = bqq.z; yr1[qq * 4 + 3] = bqq.w;
        }
        u64p s0p[2] = {0ull, 0ull}, s1p[2] = {0ull, 0ull};
#pragma unroll
        for (int k = 0; k < 16; k++) {
            u64p yap = pk2(yr0[k], yr0[k]), ybp = pk2(yr1[k], yr1[k]);
            ulonglong2 y2 = *(const ulonglong2*)&Ym[k][j0];
            s0p[0] = fma2(yap, y2.x, s0p[0]); s0p[1] = fma2(yap, y2.y, s0p[1]);
            s1p[0] = fma2(ybp, y2.x, s1p[0]); s1p[1] = fma2(ybp, y2.y, s1p[1]);
        }
        __syncwarp();
        // Yold tile = scaled g (registers)
        u64p yo0x = pk2(g0[0], g0[1]), yo0y = pk2(g0[2], g0[3]);
        u64p yo1x = pk2(g1[0], g1[1]), yo1y = pk2(g1[2], g1[3]);
        ulonglong2 ny;
        ny.x = fma2(cbp, s0p[0], mul2(cap, yo0x));
        ny.y = fma2(cbp, s0p[1], mul2(cap, yo0y));
        *(ulonglong2*)&Ym[i0][j0] = ny;
        ny.x = fma2(cbp, s1p[0], mul2(cap, yo1x));
        ny.y = fma2(cbp, s1p[1], mul2(cap, yo1y));
        *(ulonglong2*)&Ym[i0 + 1][j0] = ny;
        // Z1 = ca*I + cb*Yold (registers)
        *(float4*)&Zm[i0][j0] = make_float4(
            (i0 == j0 ? ca : 0.f) + cb * g0[0], (i0 == j0 + 1 ? ca : 0.f) + cb * g0[1],
            (i0 == j0 + 2 ? ca : 0.f) + cb * g0[2], (i0 == j0 + 3 ? ca : 0.f) + cb * g0[3]);
        *(float4*)&Zm[i0 + 1][j0] = make_float4(
            (i0 + 1 == j0 ? ca : 0.f) + cb * g1[0], (i0 + 1 == j0 + 1 ? ca : 0.f) + cb * g1[1],
            (i0 + 1 == j0 + 2 ? ca : 0.f) + cb * g1[2], (i0 + 1 == j0 + 3 ? ca : 0.f) + cb * g1[3]);
        __syncwarp();
    }

    for (int it = 1; it < ntot; it++) {
        float ca = (it < nspecial) ? ca_s : 1.5f;
        float cb = (it < nspecial) ? cb_s : -0.5f;
        bool lastit = (it == ntot - 1);
        u64p cap = pk2(ca, ca), cbp = pk2(cb, cb);

        // rows i0,i0+1 of Z into registers
        float zr0[16], zr1[16];
#pragma unroll
        for (int qq = 0; qq < 4; qq++) {
            float4 a = *(const float4*)&Zm[i0][qq * 4];
            float4 bqq = *(const float4*)&Zm[i0 + 1][qq * 4];
            zr0[qq * 4 + 0] = a.x; zr0[qq * 4 + 1] = a.y;
            zr0[qq * 4 + 2] = a.z; zr0[qq * 4 + 3] = a.w;
            zr1[qq * 4 + 0] = bqq.x; zr1[qq * 4 + 1] = bqq.y;
            zr1[qq * 4 + 2] = bqq.z; zr1[qq * 4 + 3] = bqq.w;
        }

        // M = Z*Y -> Tm (Z rows from registers, Y cols from smem)
        {
            u64p t0p[2] = {0ull, 0ull}, t1p[2] = {0ull, 0ull};
#pragma unroll
            for (int k = 0; k < 16; k++) {
                u64p z0p = pk2(zr0[k], zr0[k]), z1p = pk2(zr1[k], zr1[k]);
                ulonglong2 y2 = *(const ulonglong2*)&Ym[k][j0];
                t0p[0] = fma2(z0p, y2.x, t0p[0]); t0p[1] = fma2(z0p, y2.y, t0p[1]);
                t1p[0] = fma2(z1p, y2.x, t1p[0]); t1p[1] = fma2(z1p, y2.y, t1p[1]);
            }
            ulonglong2 tw;
            tw.x = t0p[0]; tw.y = t0p[1];
            *(ulonglong2*)&Tm[i0][j0] = tw;
            tw.x = t1p[0]; tw.y = t1p[1];
            *(ulonglong2*)&Tm[i0 + 1][j0] = tw;
        }
        __syncwarp();

        // rows of Y for the Y update (skip on last iteration)
        float yr0[16], yr1[16];
        if (!lastit) {
#pragma unroll
            for (int qq = 0; qq < 4; qq++) {
                float4 a = *(const float4*)&Ym[i0][qq * 4];
                float4 bqq = *(const float4*)&Ym[i0 + 1][qq * 4];
                yr0[qq * 4 + 0] = a.x; yr0[qq * 4 + 1] = a.y;
                yr0[qq * 4 + 2] = a.z; yr0[qq * 4 + 3] = a.w;
                yr1[qq * 4 + 0] = bqq.x; yr1[qq * 4 + 1] = bqq.y;
                yr1[qq * 4 + 2] = bqq.z; yr1[qq * 4 + 3] = bqq.w;
            }
        }

        u64p zn0p[2] = {0ull, 0ull}, zn1p[2] = {0ull, 0ull};
        u64p yn0p[2] = {0ull, 0ull}, yn1p[2] = {0ull, 0ull};
#pragma unroll
        for (int k = 0; k < 16; k++) {
            ulonglong2 m2 = *(const ulonglong2*)&Tm[k][j0];
            u64p zap = pk2(zr0[k], zr0[k]), zbp = pk2(zr1[k], zr1[k]);
            zn0p[0] = fma2(zap, m2.x, zn0p[0]); zn0p[1] = fma2(zap, m2.y, zn0p[1]);
            zn1p[0] = fma2(zbp, m2.x, zn1p[0]); zn1p[1] = fma2(zbp, m2.y, zn1p[1]);
            if (!lastit) {
                u64p yap = pk2(yr0[k], yr0[k]), ybp = pk2(yr1[k], yr1[k]);
                yn0p[0] = fma2(yap, m2.x, yn0p[0]); yn0p[1] = fma2(yap, m2.y, yn0p[1]);
                yn1p[0] = fma2(ybp, m2.x, yn1p[0]); yn1p[1] = fma2(ybp, m2.y, yn1p[1]);
            }
        }
        ulonglong2 zc0 = *(const ulonglong2*)&Zm[i0][j0];
        ulonglong2 zc1 = *(const ulonglong2*)&Zm[i0 + 1][j0];
        ulonglong2 yc0, yc1;
        if (!lastit) {
            yc0 = *(const ulonglong2*)&Ym[i0][j0];
            yc1 = *(const ulonglong2*)&Ym[i0 + 1][j0];
        }
        __syncwarp();
        ulonglong2 o;
        o.x = fma2(cbp, zn0p[0], mul2(cap, zc0.x));
        o.y = fma2(cbp, zn0p[1], mul2(cap, zc0.y));
        *(ulonglong2*)&Zm[i0][j0] = o;
        o.x = fma2(cbp, zn1p[0], mul2(cap, zc1.x));
        o.y = fma2(cbp, zn1p[1], mul2(cap, zc1.y));
        *(ulonglong2*)&Zm[i0 + 1][j0] = o;
        if (!lastit) {
            o.x = fma2(cbp, yn0p[0], mul2(cap, yc0.x));
            o.y = fma2(cbp, yn0p[1], mul2(cap, yc0.y));
            *(ulonglong2*)&Ym[i0][j0] = o;
            o.x = fma2(cbp, yn1p[0], mul2(cap, yc1.x));
            o.y = fma2(cbp, yn1p[1], mul2(cap, yc1.y));
            *(ulonglong2*)&Ym[i0 + 1][j0] = o;
        }
        __syncwarp();
    }

    // ---- U = A * Z * s^(-1/2); A rows read as float2 from smem
    float isq = rsqrtf(rs);
    u64p isqp = pk2(isq, isq);
    u64p u0p[8], u1p[8];
#pragma unroll
    for (int j = 0; j < 8; j++) { u0p[j] = 0ull; u1p[j] = 0ull; }
#pragma unroll
    for (int k = 0; k < 16; k++) {
        float2 a2 = *(const float2*)&A[k][r0];
        u64p a0p = pk2(a2.x, a2.x);
        u64p a1p = pk2(a2.y, a2.y);
#pragma unroll
        for (int cq = 0; cq < 4; cq++) {
            ulonglong2 z2 = *(const ulonglong2*)&Zm[k][cq * 4];
            u0p[cq * 2]     = fma2(a0p, z2.x, u0p[cq * 2]);
            u0p[cq * 2 + 1] = fma2(a0p, z2.y, u0p[cq * 2 + 1]);
            u1p[cq * 2]     = fma2(a1p, z2.x, u1p[cq * 2]);
            u1p[cq * 2 + 1] = fma2(a1p, z2.y, u1p[cq * 2 + 1]);
        }
    }
#pragma unroll
    for (int j = 0; j < 8; j++) {
        u0p[j] = mul2(u0p[j], isqp);
        u1p[j] = mul2(u1p[j], isqp);
    }

    // fp32 U out (lane's 128 contiguous bytes)
#pragma unroll
    for (int cq = 0; cq < 4; cq++) {
        ulonglong2 s0, s1;
        s0.x = u0p[cq * 2]; s0.y = u0p[cq * 2 + 1];
        s1.x = u1p[cq * 2]; s1.y = u1p[cq * 2 + 1];
        *(ulonglong2*)(dst + r0 * 16 + cq * 4)       = s0;
        *(ulonglong2*)(dst + (r0 + 1) * 16 + cq * 4) = s1;
    }

    // fp16 out direct (lane's 64 contiguous bytes; warp covers 2KB block)
    {
        __half* gh = g_hX[opar] + doff;
        uint32_t p[8];
#pragma unroll
        for (int j = 0; j < 8; j++) {
            float lo, hi;
            upk2(u0p[j], lo, hi);
            __half2 h2;
            h2.x = __float2half_rn(lo);
            h2.y = __float2half_rn(hi);
            p[j] = *(uint32_t*)&h2;
        }
        *(uint4*)(gh + r0 * 16)     = make_uint4(p[0], p[1], p[2], p[3]);
        *(uint4*)(gh + r0 * 16 + 8) = make_uint4(p[4], p[5], p[6], p[7]);
#pragma unroll
        for (int j = 0; j < 8; j++) {
            float lo, hi;
            upk2(u1p[j], lo, hi);
            __half2 h2;
            h2.x = __float2half_rn(lo);
            h2.y = __float2half_rn(hi);
            p[j] = *(uint32_t*)&h2;
        }
        *(uint4*)(gh + (r0 + 1) * 16)     = make_uint4(p[0], p[1], p[2], p[3]);
        *(uint4*)(gh + (r0 + 1) * 16 + 8) = make_uint4(p[4], p[5], p[6], p[7]);
    }
}

// ---------------- X_transformed transpose ------------------------------------
__global__ void xt_kernel(float* __restrict__ out) {
    __shared__ float tile[256][18];
    int base = blockIdx.x * 256;
    int tid = threadIdx.x;
#pragma unroll
    for (int l = 0; l < 17; l++)
        tile[tid][l] = g_xt[(size_t)l * PLANE + base + tid];
    __syncthreads();
    float* o = out + (size_t)base * 17;
    for (int i = tid; i < 256 * 17; i += 256)
        o[i] = tile[i / 17][i % 17];
}

// ---------------- reconstruct + classify + softmax ----------------------------
__global__ __launch_bounds__(128) void classify_kernel(
    const float* __restrict__ Wc, const float* __restrict__ bc,
    float* __restrict__ out, int off_log)
{
    __shared__ float sU[1024], sS[256], sV[1024], sT[1024];
    __shared__ float sZ[4096];
    __shared__ float red[10 * 136];
    __shared__ float slog[10];

    int b = blockIdx.x, tid = threadIdx.x;
    const float* base = g_xt + (size_t)16 * PLANE + (size_t)b * 3 * 1024;

    for (int i = tid; i < 1024; i += 128) { sU[i] = base[i]; sV[i] = base[2048 + i]; }
    for (int i = tid; i < 256; i += 128) sS[i] = base[1024 + i];
    __syncthreads();

    for (int e = tid; e < 1024; e += 128) {
        int r = e >> 4, c = e & 15;
        float sum = 0.f;
#pragma unroll
        for (int k = 0; k < 16; k++) sum += sU[r * 16 + k] * sS[k * 16 + c];
        sT[e] = sum;
    }
    __syncthreads();

    for (int e = tid; e < 4096; e += 128) {
        int r = e >> 6, qn = e & 63;
        float sum = 0.f;
#pragma unroll
        for (int c = 0; c < 16; c++) sum += sT[r * 16 + c] * sV[qn * 16 + c];
        sZ[e] = sum;
    }
    __syncthreads();

    float acc[10];
#pragma unroll
    for (int n = 0; n < 10; n++) acc[n] = 0.f;
    for (int e = tid; e < 4096; e += 128) {
        float z = sZ[e];
#pragma unroll
        for (int n = 0; n < 10; n++) acc[n] += z * Wc[n * 4096 + e];
    }
#pragma unroll
    for (int n = 0; n < 10; n++) red[n * 136 + tid] = acc[n];
    __syncthreads();
    if (tid < 10) {
        float s = bc[tid];
        for (int j = 0; j < 128; j++) s += red[tid * 136 + j];
        slog[tid] = s;
    }
    __syncthreads();
    if (tid == 0) {
        float mx = slog[0];
        for (int n = 1; n < 10; n++) mx = fmaxf(mx, slog[n]);
        float ex[10]; float se = 0.f;
        for (int n = 0; n < 10; n++) { ex[n] = expf(slog[n] - mx); se += ex[n]; }
        float inv = 1.f / se;
        for (int n = 0; n < 10; n++) {
            out[b * 10 + n] = ex[n] * inv;
            if (off_log >= 0) out[off_log + b * 10 + n] = slog[n];
        }
    }
}

// ---------------- launch ------------------------------------------------------
extern "C" void kernel_launch(void* const* d_in, const int* in_sizes, int n_in,
                              void* d_out, int out_size) {
    const float* X  = (const float*)d_in[0];
    const float* h  = (const float*)d_in[1];
    const float* W0 = (const float*)d_in[2];
    const float* Ws = (const float*)d_in[3];
    const float* bs = (const float*)d_in[4];
    const float* Wc = (const float*)d_in[5];
    const float* bc = (const float*)d_in[6];
    float* out = (float*)d_out;

    int off_log = -1, off_xt = -1;
    if (out_size >= 10240 + 10240 + 53477376) { off_log = 10240; off_xt = 20480; }
    else if (out_size == 10240 + 53477376)    { off_xt = 10240; }
    else if (out_size >= 20480)               { off_log = 10240; }

    cudaFuncSetAttribute(tgemm_kernel, cudaFuncAttributeMaxDynamicSharedMemorySize,
                         SMEM_TOTAL_G);

    wconv_kernel<<<WELEMS / 256, 256>>>(W0, Ws);
    prep_kernel<<<PLANE / 256, 256>>>(X);

    tgemm_kernel<<<256, 256, SMEM_TOTAL_G>>>(nullptr, h, 0);
    polar_kernel<<<512, 128>>>(0, 4, 5, 2.4f, -1.4f, 1);   // layer 0: 4 agg + 5 classic
    for (int l = 1; l <= 16; l++) {
        tgemm_kernel<<<256, 256, SMEM_TOTAL_G>>>(bs + (size_t)(l - 1) * 1024, h, l);
        polar_kernel<<<512, 128>>>(l, 1, 2, 1.9f, -0.9f, (l + 1) & 1);
    }

    if (off_xt >= 0)
        xt_kernel<<<PLANE / 256, 256>>>(out + off_xt);
    classify_kernel<<<1024, 128>>>(Wc, bc, out, off_log);
}

// round 15
// speedup vs baseline: 1.6025x; 1.0357x over previous
#include <cuda_runtime.h>
#include <cuda_fp16.h>
#include <math.h>
#include <stdint.h>

#define PLANE 3145728            // 3072 * 1024
#define WELEMS 17825792          // 17 * 1024 * 1024

// ---------------- device scratch --------------------------------------------
__device__ float g_Y[PLANE];                 // pre-projection Y of current layer
__device__ float g_xt[17 * PLANE];           // xs[l] planes (fp32)
__device__ __half g_hX[2][PLANE];            // ping-pong fp16 X
__device__ __half g_hW[WELEMS];              // fp16 weights (W0 at 0, Ws at 1..16)

// ---------------- helpers -----------------------------------------------------
typedef unsigned long long u64p;

static __device__ __forceinline__ uint32_t smem_u32(const void* p) {
    return (uint32_t)__cvta_generic_to_shared(p);
}
static __device__ __forceinline__ void ldsm4(uint32_t* r, uint32_t addr) {
    asm volatile("ldmatrix.sync.aligned.m8n8.x4.shared.b16 {%0,%1,%2,%3}, [%4];"
        : "=r"(r[0]), "=r"(r[1]), "=r"(r[2]), "=r"(r[3]) : "r"(addr));
}
static __device__ __forceinline__ void mma16816(float* c, const uint32_t* a,
                                                uint32_t b0, uint32_t b1) {
    asm volatile("mma.sync.aligned.m16n8k16.row.col.f32.f16.f16.f32 "
        "{%0,%1,%2,%3}, {%4,%5,%6,%7}, {%8,%9}, {%0,%1,%2,%3};"
        : "+f"(c[0]), "+f"(c[1]), "+f"(c[2]), "+f"(c[3])
        : "r"(a[0]), "r"(a[1]), "r"(a[2]), "r"(a[3]), "r"(b0), "r"(b1));
}
static __device__ __forceinline__ u64p pk2(float x, float y) {
    u64p r; asm("mov.b64 %0, {%1,%2};" : "=l"(r) : "f"(x), "f"(y)); return r;
}
static __device__ __forceinline__ void upk2(u64p v, float& x, float& y) {
    asm("mov.b64 {%0,%1}, %2;" : "=f"(x), "=f"(y) : "l"(v));
}
static __device__ __forceinline__ u64p fma2(u64p a, u64p b, u64p c) {
    u64p d; asm("fma.rn.f32x2 %0, %1, %2, %3;" : "=l"(d) : "l"(a), "l"(b), "l"(c));
    return d;
}
static __device__ __forceinline__ u64p mul2(u64p a, u64p b) {
    u64p d; asm("mul.rn.f32x2 %0, %1, %2;" : "=l"(d) : "l"(a), "l"(b));
    return d;
}

// ---------------- weight conversion (fp16) -----------------------------------
__global__ void wconv_kernel(const float* __restrict__ W0, const float* __restrict__ Ws) {
    size_t i = (size_t)blockIdx.x * 256 + threadIdx.x;
    if (i >= (size_t)WELEMS) return;
    float v = (i < 1048576) ? W0[i] : Ws[i - 1048576];
    g_hW[i] = __float2half_rn(v);
}

// ---------------- prep: fp16 of input (ch2 transposed) -----------------------
__global__ void prep_kernel(const float* __restrict__ Xin) {
    int idx = blockIdx.x * 256 + threadIdx.x;
    if (idx >= PLANE) return;
    int d  = idx & 1023;
    int bc = idx >> 10;
    int c  = bc % 3;
    float v;
    if (c == 2) {
        int b = bc / 3;
        int dim = d >> 4, k = d & 15;
        v = Xin[((size_t)(b * 3 + 2)) * 1024 + k * 64 + dim];
    } else {
        v = Xin[idx];
    }
    g_hX[0][idx] = __float2half_rn(v);
}

// ---------------- fp16 mma.sync GEMM + fused epilogue ------------------------
// Tile 96x128 (256 CTAs), K-chunk 64, 3-stage cp.async, 8 warps (2M x 4N).
#define MAT_STRIDE_B 144                 // bytes per smem row (128B data + pad)
#define A_BYTES (96 * MAT_STRIDE_B)      // 13824
#define B_BYTES (128 * MAT_STRIDE_B)     // 18432
#define STAGE_BYTES (A_BYTES + B_BYTES)  // 32256
#define SMEM_TOTAL_G (3 * STAGE_BYTES)   // 96768

__global__ __launch_bounds__(256, 2) void tgemm_kernel(
    const float* __restrict__ bias, const float* __restrict__ hp, int layer)
{
    extern __shared__ __align__(16) char smem[];
    uint32_t sb = smem_u32(smem);

    int tid = threadIdx.x;
    int wid = tid >> 5, lane = tid & 31;
    int bx = blockIdx.x;
    int m0 = (bx >> 3) * 96;
    int n0 = (bx & 7) * 128;

    int par = layer & 1;
    const __half* srcA = g_hX[par] + (size_t)m0 * 1024;
    const __half* srcB = g_hW + (size_t)layer * 1048576 + (size_t)n0 * 1024;

    float acc[3][4][4];
#pragma unroll
    for (int i = 0; i < 3; i++)
#pragma unroll
        for (int j = 0; j < 4; j++)
#pragma unroll
            for (int k = 0; k < 4; k++) acc[i][j][k] = 0.f;

    auto issue = [&](int c, int st) {
#pragma unroll
        for (int u = 0; u < 7; u++) {
            int unit = tid + u * 256;        // 0..1791
            uint32_t dst;
            const __half* gp;
            if (unit < 768) {                // A: 96 rows x 8 segs
                int row = unit >> 3, seg = unit & 7;
                dst = sb + st * STAGE_BYTES + row * MAT_STRIDE_B + seg * 16;
                gp = srcA + (size_t)row * 1024 + c * 64 + seg * 8;
            } else {                         // B: 128 rows x 8 segs
                int t = unit - 768;
                int row = t >> 3, seg = t & 7;
                dst = sb + st * STAGE_BYTES + A_BYTES + row * MAT_STRIDE_B + seg * 16;
                gp = srcB + (size_t)row * 1024 + c * 64 + seg * 8;
            }
            asm volatile("cp.async.cg.shared.global [%0], [%1], 16;"
                :: "r"(dst), "l"(gp));
        }
        asm volatile("cp.async.commit_group;" ::: "memory");
    };

    issue(0, 0);
    issue(1, 1);

    int mw = (wid >> 2) * 48, nw = (wid & 3) * 32;
    int lrow = (lane & 7) + ((lane >> 3) & 1) * 8;
    int lcolB = ((lane >> 4) * 8) * 2;

    for (int c = 0; c < 16; c++) {
        int st = c % 3;
        if (c < 15) {
            asm volatile("cp.async.wait_group 1;" ::: "memory");
        } else {
            asm volatile("cp.async.wait_group 0;" ::: "memory");
        }
        __syncthreads();
        if (c + 2 < 16) issue(c + 2, (c + 2) % 3);

        uint32_t base = sb + st * STAGE_BYTES;
#pragma unroll
        for (int ks = 0; ks < 4; ks++) {
            int colb = ks * 32 + lcolB;
            uint32_t bh[2][4];
#pragma unroll
            for (int nb = 0; nb < 2; nb++)
                ldsm4(bh[nb], base + A_BYTES +
                              (nw + nb * 16 + lrow) * MAT_STRIDE_B + colb);
#pragma unroll
            for (int ma = 0; ma < 3; ma++) {
                uint32_t ah[4];
                ldsm4(ah, base + (mw + ma * 16 + lrow) * MAT_STRIDE_B + colb);
#pragma unroll
                for (int na = 0; na < 4; na++) {
                    int nb = na >> 1, hi = na & 1;
                    mma16816(acc[ma][na], ah, bh[nb][hi], bh[nb][2 + hi]);
                }
            }
        }
    }

    // ---- fused epilogue
    float hv = 0.f;
    const float* Xprev = nullptr;
    if (layer > 0) { hv = *hp; Xprev = g_xt + (size_t)(layer - 1) * PLANE; }
    float* PL = g_xt + (size_t)layer * PLANE;
    int opar = (layer + 1) & 1;
    int g = lane >> 2, t2 = (lane & 3) * 2;

#pragma unroll
    for (int ma = 0; ma < 3; ma++) {
#pragma unroll
        for (int na = 0; na < 4; na++) {
            int n = n0 + nw + na * 8 + t2;
            float2 b2 = make_float2(0.f, 0.f);
            if (layer > 0) b2 = *(const float2*)(bias + n);
#pragma unroll
            for (int hh = 0; hh < 2; hh++) {
                int m = m0 + mw + ma * 16 + g + hh * 8;
                float cx = acc[ma][na][hh * 2], cy = acc[ma][na][hh * 2 + 1];
                float2 y;
                if (layer > 0) {
                    float2 xo = *(const float2*)(Xprev + (size_t)m * 1024 + n);
                    y.x = xo.x + hv * fmaxf(cx + b2.x, 0.f);
                    y.y = xo.y + hv * fmaxf(cy + b2.y, 0.f);
                } else {
                    y.x = cx; y.y = cy;
                }
                if (m % 3 == 1) {          // S channel: no projection
                    *(float2*)(PL + (size_t)m * 1024 + n) = y;
                    __half2 h2;
                    h2.x = __float2half_rn(y.x);
                    h2.y = __float2half_rn(y.y);
                    *(__half2*)(&g_hX[opar][(size_t)m * 1024 + n]) = h2;
                } else {                   // U/V channels: polar input only
                    *(float2*)(g_Y + (size_t)m * 1024 + n) = y;
                }
            }
        }
    }
}

// ---------------- polar projection (NS, smem-op minimized) -------------------
#define PNW 4
__global__ __launch_bounds__(128) void polar_kernel(int plane, int nspecial,
                                                    int nclassic, float ca_s,
                                                    float cb_s, int opar) {
    __shared__ float AsP[PNW][16][68];
    __shared__ float MsP[PNW][3][16][20];

    int w = threadIdx.x >> 5, lane = threadIdx.x & 31;
    int idx = blockIdx.x * PNW + w;
    int b = idx >> 1, ch = (idx & 1) * 2;

    const float* src = g_Y + (size_t)(b * 3 + ch) * 1024;
    size_t doff = (size_t)(b * 3 + ch) * 1024;
    float* dst = g_xt + (size_t)plane * PLANE + doff;

    float (*A)[68]  = AsP[w];
    float (*Ym)[20] = MsP[w][0];
    float (*Zm)[20] = MsP[w][1];
    float (*Tm)[20] = MsP[w][2];

    int r0 = lane * 2;
#pragma unroll
    for (int qq = 0; qq < 4; qq++) {
        float4 v0 = *(const float4*)(src + r0 * 16 + qq * 4);
        float4 v1 = *(const float4*)(src + (r0 + 1) * 16 + qq * 4);
        *(float2*)&A[qq * 4 + 0][r0] = make_float2(v0.x, v1.x);
        *(float2*)&A[qq * 4 + 1][r0] = make_float2(v0.y, v1.y);
        *(float2*)&A[qq * 4 + 2][r0] = make_float2(v0.z, v1.z);
        *(float2*)&A[qq * 4 + 3][r0] = make_float2(v0.w, v1.w);
    }
    __syncwarp();

    int i0 = (lane >> 2) * 2, j0 = (lane & 3) * 4;

    u64p gp0[4], gp1[4];
#pragma unroll
    for (int t = 0; t < 4; t++) { gp0[t] = 0ull; gp1[t] = 0ull; }
#pragma unroll
    for (int r = 0; r < 64; r += 4) {
        ulonglong2 a0 = *(const ulonglong2*)&A[i0][r];
        ulonglong2 a1 = *(const ulonglong2*)&A[i0 + 1][r];
#pragma unroll
        for (int t = 0; t < 4; t++) {
            ulonglong2 aj = *(const ulonglong2*)&A[j0 + t][r];
            gp0[t] = fma2(a0.x, aj.x, gp0[t]);
            gp0[t] = fma2(a0.y, aj.y, gp0[t]);
            gp1[t] = fma2(a1.x, aj.x, gp1[t]);
            gp1[t] = fma2(a1.y, aj.y, gp1[t]);
        }
    }
    float g0[4], g1[4];
#pragma unroll
    for (int t = 0; t < 4; t++) {
        float lo, hi;
        upk2(gp0[t], lo, hi); g0[t] = lo + hi;
        upk2(gp1[t], lo, hi); g1[t] = lo + hi;
    }

    float rs0 = fabsf(g0[0]) + fabsf(g0[1]) + fabsf(g0[2]) + fabsf(g0[3]);
    float rs1 = fabsf(g1[0]) + fabsf(g1[1]) + fabsf(g1[2]) + fabsf(g1[3]);
    rs0 += __shfl_xor_sync(0xffffffffu, rs0, 1);
    rs0 += __shfl_xor_sync(0xffffffffu, rs0, 2);
    rs1 += __shfl_xor_sync(0xffffffffu, rs1, 1);
    rs1 += __shfl_xor_sync(0xffffffffu, rs1, 2);
    float rs = fmaxf(rs0, rs1);
    rs = fmaxf(rs, __shfl_xor_sync(0xffffffffu, rs, 4));
    rs = fmaxf(rs, __shfl_xor_sync(0xffffffffu, rs, 8));
    rs = fmaxf(rs, __shfl_xor_sync(0xffffffffu, rs, 16));
    float invs = 1.0f / rs;

#pragma unroll
    for (int t = 0; t < 4; t++) { g0[t] *= invs; g1[t] *= invs; }
    *(float4*)&Ym[i0][j0]     = make_float4(g0[0], g0[1], g0[2], g0[3]);
    *(float4*)&Ym[i0 + 1][j0] = make_float4(g1[0], g1[1], g1[2], g1[3]);
    __syncwarp();

    int ntot = nspecial + nclassic;

    {
        float ca = (0 < nspecial) ? ca_s : 1.5f;
        float cb = (0 < nspecial) ? cb_s : -0.5f;
        u64p cap = pk2(ca, ca), cbp = pk2(cb, cb);
        float yr0[16], yr1[16];
#pragma unroll
        for (int qq = 0; qq < 4; qq++) {
            float4 a = *(const float4*)&Ym[i0][qq * 4];
            float4 bqq = *(const float4*)&Ym[i0 + 1][qq * 4];
            yr0[qq * 4 + 0] = a.x; yr0[qq * 4 + 1] = a.y;
            yr0[qq * 4 + 2] = a.z; yr0[qq * 4 + 3] = a.w;
            yr1[qq * 4 + 0] = bqq.x; yr1[qq * 4 + 1] = bqq.y;
            yr1[qq * 4 + 2] = bqq.z; yr1[qq * 4 + 3] = bqq.w;
        }
        u64p s0p[2] = {0ull, 0ull}, s1p[2] = {0ull, 0ull};
#pragma unroll
        for (int k = 0; k < 16; k++) {
            u64p yap = pk2(yr0[k], yr0[k]), ybp = pk2(yr1[k], yr1[k]);
            ulonglong2 y2 = *(const ulonglong2*)&Ym[k][j0];
            s0p[0] = fma2(yap, y2.x, s0p[0]); s0p[1] = fma2(yap, y2.y, s0p[1]);
            s1p[0] = fma2(ybp, y2.x, s1p[0]); s1p[1] = fma2(ybp, y2.y, s1p[1]);
        }
        __syncwarp();
        u64p yo0x = pk2(g0[0], g0[1]), yo0y = pk2(g0[2], g0[3]);
        u64p yo1x = pk2(g1[0], g1[1]), yo1y = pk2(g1[2], g1[3]);
        ulonglong2 ny;
        ny.x = fma2(cbp, s0p[0], mul2(cap, yo0x));
        ny.y = fma2(cbp, s0p[1], mul2(cap, yo0y));
        *(ulonglong2*)&Ym[i0][j0] = ny;
        ny.x = fma2(cbp, s1p[0], mul2(cap, yo1x));
        ny.y = fma2(cbp, s1p[1], mul2(cap, yo1y));
        *(ulonglong2*)&Ym[i0 + 1][j0] = ny;
        *(float4*)&Zm[i0][j0] = make_float4(
            (i0 == j0 ? ca : 0.f) + cb * g0[0], (i0 == j0 + 1 ? ca : 0.f) + cb * g0[1],
            (i0 == j0 + 2 ? ca : 0.f) + cb * g0[2], (i0 == j0 + 3 ? ca : 0.f) + cb * g0[3]);
        *(float4*)&Zm[i0 + 1][j0] = make_float4(
            (i0 + 1 == j0 ? ca : 0.f) + cb * g1[0], (i0 + 1 == j0 + 1 ? ca : 0.f) + cb * g1[1],
            (i0 + 1 == j0 + 2 ? ca : 0.f) + cb * g1[2], (i0 + 1 == j0 + 3 ? ca : 0.f) + cb * g1[3]);
        __syncwarp();
    }

    for (int it = 1; it < ntot; it++) {
        float ca = (it < nspecial) ? ca_s : 1.5f;
        float cb = (it < nspecial) ? cb_s : -0.5f;
        bool lastit = (it == ntot - 1);
        u64p cap = pk2(ca, ca), cbp = pk2(cb, cb);

        float zr0[16], zr1[16];
#pragma unroll
        for (int qq = 0; qq < 4; qq++) {
            float4 a = *(const float4*)&Zm[i0][qq * 4];
            float4 bqq = *(const float4*)&Zm[i0 + 1][qq * 4];
            zr0[qq * 4 + 0] = a.x; zr0[qq * 4 + 1] = a.y;
            zr0[qq * 4 + 2] = a.z; zr0[qq * 4 + 3] = a.w;
            zr1[qq * 4 + 0] = bqq.x; zr1[qq * 4 + 1] = bqq.y;
            zr1[qq * 4 + 2] = bqq.z; zr1[qq * 4 + 3] = bqq.w;
        }

        {
            u64p t0p[2] = {0ull, 0ull}, t1p[2] = {0ull, 0ull};
#pragma unroll
            for (int k = 0; k < 16; k++) {
                u64p z0p = pk2(zr0[k], zr0[k]), z1p = pk2(zr1[k], zr1[k]);
                ulonglong2 y2 = *(const ulonglong2*)&Ym[k][j0];
                t0p[0] = fma2(z0p, y2.x, t0p[0]); t0p[1] = fma2(z0p, y2.y, t0p[1]);
                t1p[0] = fma2(z1p, y2.x, t1p[0]); t1p[1] = fma2(z1p, y2.y, t1p[1]);
            }
            ulonglong2 tw;
            tw.x = t0p[0]; tw.y = t0p[1];
            *(ulonglong2*)&Tm[i0][j0] = tw;
            tw.x = t1p[0]; tw.y = t1p[1];
            *(ulonglong2*)&Tm[i0 + 1][j0] = tw;
        }
        __syncwarp();

        float yr0[16], yr1[16];
        if (!lastit) {
#pragma unroll
            for (int qq = 0; qq < 4; qq++) {
                float4 a = *(const float4*)&Ym[i0][qq * 4];
                float4 bqq = *(const float4*)&Ym[i0 + 1][qq * 4];
                yr0[qq * 4 + 0] = a.x; yr0[qq * 4 + 1] = a.y;
                yr0[qq * 4 + 2] = a.z; yr0[qq * 4 + 3] = a.w;
                yr1[qq * 4 + 0] = bqq.x; yr1[qq * 4 + 1] = bqq.y;
                yr1[qq * 4 + 2] = bqq.z; yr1[qq * 4 + 3] = bqq.w;
            }
        }

        u64p zn0p[2] = {0ull, 0ull}, zn1p[2] = {0ull, 0ull};
        u64p yn0p[2] = {0ull, 0ull}, yn1p[2] = {0ull, 0ull};
#pragma unroll
        for (int k = 0; k < 16; k++) {
            ulonglong2 m2 = *(const ulonglong2*)&Tm[k][j0];
            u64p zap = pk2(zr0[k], zr0[k]), zbp = pk2(zr1[k], zr1[k]);
            zn0p[0] = fma2(zap, m2.x, zn0p[0]); zn0p[1] = fma2(zap, m2.y, zn0p[1]);
            zn1p[0] = fma2(zbp, m2.x, zn1p[0]); zn1p[1] = fma2(zbp, m2.y, zn1p[1]);
            if (!lastit) {
                u64p yap = pk2(yr0[k], yr0[k]), ybp = pk2(yr1[k], yr1[k]);
                yn0p[0] = fma2(yap, m2.x, yn0p[0]); yn0p[1] = fma2(yap, m2.y, yn0p[1]);
                yn1p[0] = fma2(ybp, m2.x, yn1p[0]); yn1p[1] = fma2(ybp, m2.y, yn1p[1]);
            }
        }
        ulonglong2 zc0 = *(const ulonglong2*)&Zm[i0][j0];
        ulonglong2 zc1 = *(const ulonglong2*)&Zm[i0 + 1][j0];
        ulonglong2 yc0, yc1;
        if (!lastit) {
            yc0 = *(const ulonglong2*)&Ym[i0][j0];
            yc1 = *(const ulonglong2*)&Ym[i0 + 1][j0];
        }
        __syncwarp();
        ulonglong2 o;
        o.x = fma2(cbp, zn0p[0], mul2(cap, zc0.x));
        o.y = fma2(cbp, zn0p[1], mul2(cap, zc0.y));
        *(ulonglong2*)&Zm[i0][j0] = o;
        o.x = fma2(cbp, zn1p[0], mul2(cap, zc1.x));
        o.y = fma2(cbp, zn1p[1], mul2(cap, zc1.y));
        *(ulonglong2*)&Zm[i0 + 1][j0] = o;
        if (!lastit) {
            o.x = fma2(cbp, yn0p[0], mul2(cap, yc0.x));
            o.y = fma2(cbp, yn0p[1], mul2(cap, yc0.y));
            *(ulonglong2*)&Ym[i0][j0] = o;
            o.x = fma2(cbp, yn1p[0], mul2(cap, yc1.x));
            o.y = fma2(cbp, yn1p[1], mul2(cap, yc1.y));
            *(ulonglong2*)&Ym[i0 + 1][j0] = o;
        }
        __syncwarp();
    }

    float isq = rsqrtf(rs);
    u64p isqp = pk2(isq, isq);
    u64p u0p[8], u1p[8];
#pragma unroll
    for (int j = 0; j < 8; j++) { u0p[j] = 0ull; u1p[j] = 0ull; }
#pragma unroll
    for (int k = 0; k < 16; k++) {
        float2 a2 = *(const float2*)&A[k][r0];
        u64p a0p = pk2(a2.x, a2.x);
        u64p a1p = pk2(a2.y, a2.y);
#pragma unroll
        for (int cq = 0; cq < 4; cq++) {
            ulonglong2 z2 = *(const ulonglong2*)&Zm[k][cq * 4];
            u0p[cq * 2]     = fma2(a0p, z2.x, u0p[cq * 2]);
            u0p[cq * 2 + 1] = fma2(a0p, z2.y, u0p[cq * 2 + 1]);
            u1p[cq * 2]     = fma2(a1p, z2.x, u1p[cq * 2]);
            u1p[cq * 2 + 1] = fma2(a1p, z2.y, u1p[cq * 2 + 1]);
        }
    }
#pragma unroll
    for (int j = 0; j < 8; j++) {
        u0p[j] = mul2(u0p[j], isqp);
        u1p[j] = mul2(u1p[j], isqp);
    }

#pragma unroll
    for (int cq = 0; cq < 4; cq++) {
        ulonglong2 s0, s1;
        s0.x = u0p[cq * 2]; s0.y = u0p[cq * 2 + 1];
        s1.x = u1p[cq * 2]; s1.y = u1p[cq * 2 + 1];
        *(ulonglong2*)(dst + r0 * 16 + cq * 4)       = s0;
        *(ulonglong2*)(dst + (r0 + 1) * 16 + cq * 4) = s1;
    }

    {
        __half* gh = g_hX[opar] + doff;
        uint32_t p[8];
#pragma unroll
        for (int j = 0; j < 8; j++) {
            float lo, hi;
            upk2(u0p[j], lo, hi);
            __half2 h2;
            h2.x = __float2half_rn(lo);
            h2.y = __float2half_rn(hi);
            p[j] = *(uint32_t*)&h2;
        }
        *(uint4*)(gh + r0 * 16)     = make_uint4(p[0], p[1], p[2], p[3]);
        *(uint4*)(gh + r0 * 16 + 8) = make_uint4(p[4], p[5], p[6], p[7]);
#pragma unroll
        for (int j = 0; j < 8; j++) {
            float lo, hi;
            upk2(u1p[j], lo, hi);
            __half2 h2;
            h2.x = __float2half_rn(lo);
            h2.y = __float2half_rn(hi);
            p[j] = *(uint32_t*)&h2;
        }
        *(uint4*)(gh + (r0 + 1) * 16)     = make_uint4(p[0], p[1], p[2], p[3]);
        *(uint4*)(gh + (r0 + 1) * 16 + 8) = make_uint4(p[4], p[5], p[6], p[7]);
    }
}

// ---------------- X_transformed transpose (float4 stores) --------------------
__global__ void xt_kernel(float* __restrict__ out) {
    __shared__ float tile[256][18];
    int base = blockIdx.x * 256;
    int tid = threadIdx.x;
#pragma unroll
    for (int l = 0; l < 17; l++)
        tile[tid][l] = g_xt[(size_t)l * PLANE + base + tid];
    __syncthreads();
    float4* o4 = (float4*)(out + (size_t)base * 17);
    for (int i = tid; i < 1088; i += 256) {     // 4352 floats = 1088 float4
        int e = i * 4;
        float4 v;
        v.x = tile[e / 17][e % 17];
        v.y = tile[(e + 1) / 17][(e + 1) % 17];
        v.z = tile[(e + 2) / 17][(e + 2) % 17];
        v.w = tile[(e + 3) / 17][(e + 3) % 17];
        o4[i] = v;
    }
}

// ---------------- reconstruct + classify + softmax ----------------------------
__global__ __launch_bounds__(128) void classify_kernel(
    const float* __restrict__ Wc, const float* __restrict__ bc,
    float* __restrict__ out, int off_log)
{
    __shared__ float sU[1024], sS[256], sV[1024], sT[1024];
    __shared__ float sZ[4096];
    __shared__ float red[10 * 136];
    __shared__ float slog[10];

    int b = blockIdx.x, tid = threadIdx.x;
    const float* base = g_xt + (size_t)16 * PLANE + (size_t)b * 3 * 1024;

    for (int i = tid; i < 1024; i += 128) { sU[i] = base[i]; sV[i] = base[2048 + i]; }
    for (int i = tid; i < 256; i += 128) sS[i] = base[1024 + i];
    __syncthreads();

    for (int e = tid; e < 1024; e += 128) {
        int r = e >> 4, c = e & 15;
        float sum = 0.f;
#pragma unroll
        for (int k = 0; k < 16; k++) sum += sU[r * 16 + k] * sS[k * 16 + c];
        sT[e] = sum;
    }
    __syncthreads();

    for (int e = tid; e < 4096; e += 128) {
        int r = e >> 6, qn = e & 63;
        float sum = 0.f;
#pragma unroll
        for (int c = 0; c < 16; c++) sum += sT[r * 16 + c] * sV[qn * 16 + c];
        sZ[e] = sum;
    }
    __syncthreads();

    float acc[10];
#pragma unroll
    for (int n = 0; n < 10; n++) acc[n] = 0.f;
    for (int e = tid; e < 4096; e += 128) {
        float z = sZ[e];
#pragma unroll
        for (int n = 0; n < 10; n++) acc[n] += z * Wc[n * 4096 + e];
    }
#pragma unroll
    for (int n = 0; n < 10; n++) red[n * 136 + tid] = acc[n];
    __syncthreads();
    if (tid < 10) {
        float s = bc[tid];
        for (int j = 0; j < 128; j++) s += red[tid * 136 + j];
        slog[tid] = s;
    }
    __syncthreads();
    if (tid == 0) {
        float mx = slog[0];
        for (int n = 1; n < 10; n++) mx = fmaxf(mx, slog[n]);
        float ex[10]; float se = 0.f;
        for (int n = 0; n < 10; n++) { ex[n] = expf(slog[n] - mx); se += ex[n]; }
        float inv = 1.f / se;
        for (int n = 0; n < 10; n++) {
            out[b * 10 + n] = ex[n] * inv;
            if (off_log >= 0) out[off_log + b * 10 + n] = slog[n];
        }
    }
}

// ---------------- launch ------------------------------------------------------
extern "C" void kernel_launch(void* const* d_in, const int* in_sizes, int n_in,
                              void* d_out, int out_size) {
    const float* X  = (const float*)d_in[0];
    const float* h  = (const float*)d_in[1];
    const float* W0 = (const float*)d_in[2];
    const float* Ws = (const float*)d_in[3];
    const float* bs = (const float*)d_in[4];
    const float* Wc = (const float*)d_in[5];
    const float* bc = (const float*)d_in[6];
    float* out = (float*)d_out;

    int off_log = -1, off_xt = -1;
    if (out_size >= 10240 + 10240 + 53477376) { off_log = 10240; off_xt = 20480; }
    else if (out_size == 10240 + 53477376)    { off_xt = 10240; }
    else if (out_size >= 20480)               { off_log = 10240; }

    cudaFuncSetAttribute(tgemm_kernel, cudaFuncAttributeMaxDynamicSharedMemorySize,
                         SMEM_TOTAL_G);

    wconv_kernel<<<WELEMS / 256, 256>>>(W0, Ws);
    prep_kernel<<<PLANE / 256, 256>>>(X);

    tgemm_kernel<<<256, 256, SMEM_TOTAL_G>>>(nullptr, h, 0);
    polar_kernel<<<512, 128>>>(0, 4, 5, 2.4f, -1.4f, 1);   // layer 0: 4 agg + 5 classic
    for (int l = 1; l <= 16; l++) {
        tgemm_kernel<<<256, 256, SMEM_TOTAL_G>>>(bs + (size_t)(l - 1) * 1024, h, l);
        polar_kernel<<<512, 128>>>(l, 1, 2, 1.9f, -0.9f, (l + 1) & 1);
    }

    if (off_xt >= 0)
        xt_kernel<<<PLANE / 256, 256>>>(out + off_xt);
    classify_kernel<<<1024, 128>>>(Wc, bc, out, off_log);
}